// round 12
// baseline (speedup 1.0000x reference)
#include <cuda_runtime.h>
#include <cuda_bf16.h>
#include <cstdint>

#define Nb 8
#define LL 4096
#define SS 4096
#define EE 256
#define HH 8
#define DD 32
#define NTOK (Nb*LL)
#define EPSV 1e-6f
#define NCHUNK 8
#define CHS (SS/NCHUNK)

typedef unsigned short ushortT;

// ---------------- scratch ----------------
__device__ float g_part[NCHUNK*Nb*HH*1056];
__device__ float g_KV[Nb*HH*1056];     // only Ksum range [1024..1055] consumed downstream
__device__ int   g_mask_kind;
#define MATU 147456                    // ushorts per 256x256 split matrix
__device__ ushortT g_Wsp[3*MATU];      // Wq, Wk, Wv  (tiled hi/lo bf16)
__device__ ushortT g_UTsp[Nb*MATU];    // per-batch UT (tiled hi/lo bf16)
__device__ ushortT g_Qsp[(NTOK/128)*73728];  // Qf*Z split-tiled
// K/V feature planes: per (n,h): [S rows x 40 ushorts] (32 cols + 8 pad), hi and lo
#define KVP_PITCH 40
#define KVPLANE ((size_t)Nb*HH*SS*KVP_PITCH)
__device__ ushortT g_Ksp_hi[KVPLANE];
__device__ ushortT g_Ksp_lo[KVPLANE];
__device__ ushortT g_Vsp_hi[KVPLANE];
__device__ ushortT g_Vsp_lo[KVPLANE];

// ---------------- helpers ----------------
__device__ __forceinline__ uint32_t smem_u32(const void* p) {
    uint32_t a;
    asm("{ .reg .u64 t; cvta.to.shared.u64 t, %1; cvt.u32.u64 %0, t; }" : "=r"(a) : "l"(p));
    return a;
}
__device__ __forceinline__ void ldsm4(unsigned* r, uint32_t addr) {
    asm volatile("ldmatrix.sync.aligned.m8n8.x4.shared.b16 {%0,%1,%2,%3}, [%4];"
        : "=r"(r[0]), "=r"(r[1]), "=r"(r[2]), "=r"(r[3]) : "r"(addr));
}
__device__ __forceinline__ void ldsm4t(unsigned* r, uint32_t addr) {
    asm volatile("ldmatrix.sync.aligned.m8n8.x4.trans.shared.b16 {%0,%1,%2,%3}, [%4];"
        : "=r"(r[0]), "=r"(r[1]), "=r"(r[2]), "=r"(r[3]) : "r"(addr));
}
__device__ __forceinline__ void ldsm2t(unsigned* r, uint32_t addr) {
    asm volatile("ldmatrix.sync.aligned.m8n8.x2.trans.shared.b16 {%0,%1}, [%2];"
        : "=r"(r[0]), "=r"(r[1]) : "r"(addr));
}
__device__ __forceinline__ void mma16816(float* c, const unsigned* a, const unsigned* b) {
    asm volatile("mma.sync.aligned.m16n8k16.row.col.f32.bf16.bf16.f32 "
        "{%0,%1,%2,%3}, {%4,%5,%6,%7}, {%8,%9}, {%0,%1,%2,%3};"
        : "+f"(c[0]), "+f"(c[1]), "+f"(c[2]), "+f"(c[3])
        : "r"(a[0]), "r"(a[1]), "r"(a[2]), "r"(a[3]), "r"(b[0]), "r"(b[1]));
}
__device__ __forceinline__ uint2 splitpack(float x0, float x1) {
    __nv_bfloat162 h = __float22bfloat162_rn(make_float2(x0, x1));
    float2 hf = __bfloat1622float2(h);
    __nv_bfloat162 l = __float22bfloat162_rn(make_float2(x0 - hf.x, x1 - hf.y));
    uint2 o;
    o.x = *(unsigned*)&h;
    o.y = *(unsigned*)&l;
    return o;
}

// ---------------- mask dtype detection ----------------
__global__ void detect_mask_kernel(const unsigned int* __restrict__ m, int nwords) {
    __shared__ int flags[3];
    if (threadIdx.x < 3) flags[threadIdx.x] = 0;
    __syncthreads();
    for (int i = threadIdx.x; i < nwords; i += blockDim.x) {
        unsigned w = m[i];
        if (w == 0x3F803F80u || w == 0x00003F80u) atomicOr(&flags[0], 1);
        else if (w == 0x3F800000u) atomicOr(&flags[1], 1);
        else if (w > 1u) {
            unsigned b0 = w & 255u, b1 = (w >> 8) & 255u, b2 = (w >> 16) & 255u, b3 = w >> 24;
            if (b0 <= 1u && b1 <= 1u && b2 <= 1u && b3 <= 1u) atomicOr(&flags[2], 1);
        }
    }
    __syncthreads();
    if (threadIdx.x == 0) {
        int kind;
        if (flags[0]) kind = 3;
        else if (flags[1]) kind = 2;
        else if (flags[2]) kind = 0;
        else kind = 1;
        g_mask_kind = kind;
    }
}

__device__ __forceinline__ float mask_val(const void* p, int i) {
    int k = g_mask_kind;
    if (k == 0) return ((const unsigned char*)p)[i] ? 1.f : 0.f;
    if (k == 1) return ((const int*)p)[i] ? 1.f : 0.f;
    if (k == 2) return ((const float*)p)[i];
    return __bfloat162float(((const __nv_bfloat16*)p)[i]);
}

// ---------------- pre-split the 3 weight matrices ----------------
__global__ __launch_bounds__(256) void split_w3(const float* __restrict__ W0,
                                                const float* __restrict__ W1,
                                                const float* __restrict__ W2) {
    int y = blockIdx.y;
    const float* src = y == 0 ? W0 : (y == 1 ? W1 : W2);
    ushortT* dst = g_Wsp + (size_t)y * MATU;
    int blk = blockIdx.x >> 1;
    int half = blockIdx.x & 1;
    int nh2 = blk >> 2, kc = blk & 3;
    int tid = threadIdx.x;
    size_t ubase = (size_t)blk * 18432;
#pragma unroll
    for (int i = 0; i < 4; i++) {
        int idx = tid + i * 256;
        int r = half * 64 + (idx >> 4), c4 = (idx & 15) * 4;
        float4 v = *(const float4*)&src[(size_t)(nh2 * 128 + r) * EE + kc * 64 + c4];
        uint2 s0 = splitpack(v.x, v.y);
        uint2 s1 = splitpack(v.z, v.w);
        ushortT* hp = dst + ubase + r * 72 + c4;
        *(unsigned*)hp = s0.x; *(unsigned*)(hp + 2) = s1.x;
        ushortT* lp = hp + 9216;
        *(unsigned*)lp = s0.y; *(unsigned*)(lp + 2) = s1.y;
    }
}

// ================= pipelined mma.sync split-bf16 GEMM (projections) =================
#define EPI_FEAT  1   // elu+1, mask -> split planes (K)
#define EPI_VPROJ 2   // (x+b)*mask*scale -> split planes (V)
#define EPI_QZ    3   // elu+1, mask, fold Z, write split-tiled g_Qsp
#define PITCHB 144
#define TILEB (128*PITCHB)    // 18432 B
#define BSTAGE (2*TILEB)
#define SMEM_SZ (2*TILEB + 2*BSTAGE)   // 110592 B

extern __shared__ char dyn_smem[];

__global__ void __launch_bounds__(512, 2) tgemm(
    const float* __restrict__ A0, const float* __restrict__ A1,
    const ushortT* __restrict__ Bsp, int bStrideZ,
    const float* __restrict__ bias0, const float* __restrict__ bias1,
    int epi0, int epi1,
    const void* __restrict__ mask, float scale)
{
    int z = blockIdx.z;
    const float* A    = z == 0 ? A0 : A1;
    const float* bias = z == 0 ? bias0 : bias1;
    int epi           = z == 0 ? epi0 : epi1;

    uint32_t AhU = smem_u32(dyn_smem);
    uint32_t AlU = AhU + TILEB;
    uint32_t BsU = AhU + 2 * TILEB;

    int tid = threadIdx.x, wid = tid >> 5, lane = tid & 31;
    int wm = wid >> 2, wn = wid & 3;
    int bm = blockIdx.y * 128, bn = blockIdx.x * 128;
    const ushortT* B = Bsp + (size_t)z * bStrideZ;

    int lmat = lane >> 3, lrow = lane & 7;
    int a_roff = ((lmat & 1) ? 8 : 0) + lrow;
    int a_coff = (lmat & 2) ? 16 : 0;
    int b_roff = ((lmat & 2) ? 8 : 0) + lrow;
    int b_coff = (lmat & 1) ? 16 : 0;

    float acc[2][4][4];
#pragma unroll
    for (int mi = 0; mi < 2; mi++)
#pragma unroll
        for (int ni = 0; ni < 4; ni++)
#pragma unroll
            for (int j = 0; j < 4; j++) acc[mi][ni][j] = 0.f;

    float4 pf[4];

#define ISSUE_B(kc, stage) do { \
        const char* _src = (const char*)(B + (size_t)(blockIdx.x * 4 + (kc)) * 18432); \
        uint32_t _db = BsU + (stage) * BSTAGE; \
        _Pragma("unroll") \
        for (int _j = 0; _j < 5; _j++) { \
            int _id = tid + _j * 512; \
            if (_id < 2304) \
                asm volatile("cp.async.cg.shared.global [%0], [%1], 16;" \
                    :: "r"(_db + _id * 16), "l"(_src + _id * 16)); \
        } \
        asm volatile("cp.async.commit_group;" ::: "memory"); \
    } while (0)

#define LOAD_A(kc) do { \
        _Pragma("unroll") \
        for (int _i = 0; _i < 4; _i++) { \
            int _idx = tid + _i * 512; \
            int _r = _idx >> 4, _c4 = (_idx & 15) << 2; \
            pf[_i] = *(const float4*)&A[(size_t)(bm + _r) * EE + (kc) * 64 + _c4]; \
        } \
    } while (0)

#define STORE_A() do { \
        _Pragma("unroll") \
        for (int _i = 0; _i < 4; _i++) { \
            int _idx = tid + _i * 512; \
            int _r = _idx >> 4, _c4 = (_idx & 15) << 2; \
            uint32_t _off = _r * PITCHB + _c4 * 2; \
            uint2 _s0 = splitpack(pf[_i].x, pf[_i].y); \
            uint2 _s1 = splitpack(pf[_i].z, pf[_i].w); \
            asm volatile("st.shared.v2.b32 [%0], {%1,%2};" :: "r"(AhU + _off), "r"(_s0.x), "r"(_s1.x) : "memory"); \
            asm volatile("st.shared.v2.b32 [%0], {%1,%2};" :: "r"(AlU + _off), "r"(_s0.y), "r"(_s1.y) : "memory"); \
        } \
    } while (0)

    ISSUE_B(0, 0);
    LOAD_A(0);
    STORE_A();
    asm volatile("cp.async.wait_group 0;" ::: "memory");
    __syncthreads();

    for (int kc = 0; kc < 4; kc++) {
        int s = kc & 1;
        if (kc < 3) {
            ISSUE_B(kc + 1, s ^ 1);
            LOAD_A(kc + 1);
        }
        uint32_t BhU = BsU + s * BSTAGE;
        uint32_t BlU = BhU + TILEB;
#pragma unroll
        for (int ks = 0; ks < 4; ks++) {
            int cbb = ks * 32;
            unsigned ah[2][4], bh[4][2], bx[4][2], tmp[4];
#pragma unroll
            for (int mi = 0; mi < 2; mi++) {
                int rb = wm * 32 + mi * 16;
                ldsm4(ah[mi], AhU + (rb + a_roff) * PITCHB + cbb + a_coff);
            }
#pragma unroll
            for (int p = 0; p < 2; p++) {
                int nb = wn * 32 + p * 16;
                ldsm4(tmp, BhU + (nb + b_roff) * PITCHB + cbb + b_coff);
                bh[2*p][0] = tmp[0]; bh[2*p][1] = tmp[1];
                bh[2*p+1][0] = tmp[2]; bh[2*p+1][1] = tmp[3];
            }
#pragma unroll
            for (int mi = 0; mi < 2; mi++)
#pragma unroll
                for (int ni = 0; ni < 4; ni++) mma16816(acc[mi][ni], ah[mi], bh[ni]);
#pragma unroll
            for (int p = 0; p < 2; p++) {
                int nb = wn * 32 + p * 16;
                ldsm4(tmp, BlU + (nb + b_roff) * PITCHB + cbb + b_coff);
                bx[2*p][0] = tmp[0]; bx[2*p][1] = tmp[1];
                bx[2*p+1][0] = tmp[2]; bx[2*p+1][1] = tmp[3];
            }
#pragma unroll
            for (int mi = 0; mi < 2; mi++)
#pragma unroll
                for (int ni = 0; ni < 4; ni++) mma16816(acc[mi][ni], ah[mi], bx[ni]);
#pragma unroll
            for (int mi = 0; mi < 2; mi++) {
                int rb = wm * 32 + mi * 16;
                ldsm4(ah[mi], AlU + (rb + a_roff) * PITCHB + cbb + a_coff);
            }
#pragma unroll
            for (int mi = 0; mi < 2; mi++)
#pragma unroll
                for (int ni = 0; ni < 4; ni++) mma16816(acc[mi][ni], ah[mi], bh[ni]);
        }
        __syncthreads();
        if (kc < 3) {
            STORE_A();
            asm volatile("cp.async.wait_group 0;" ::: "memory");
            __syncthreads();
        }
    }

    // ---- epilogue ----
    int g = lane >> 2, tc = lane & 3;
    if (epi == EPI_QZ) {
        int n = bm >> 12;
        int h = (bn + wn * 32) >> 5;
        const float* ksp = g_KV + (size_t)(n * HH + h) * 1056 + 1024;
        int rbblk = bm >> 7;
#pragma unroll
        for (int mi = 0; mi < 2; mi++) {
            int r0 = bm + wm * 32 + mi * 16 + g;
            int r1 = r0 + 8;
            float mv0 = mask_val(mask, r0), mv1 = mask_val(mask, r1);
            float cb[4][4];
            float p0 = 0.f, p1 = 0.f;
#pragma unroll
            for (int ni = 0; ni < 4; ni++) {
                int col = bn + wn * 32 + ni * 8 + tc * 2;
                int d = ni * 8 + tc * 2;
                float b0 = bias[col], b1 = bias[col + 1];
                float c0 = acc[mi][ni][0] + b0, c1 = acc[mi][ni][1] + b1;
                float c2 = acc[mi][ni][2] + b0, c3 = acc[mi][ni][3] + b1;
                c0 = (c0 > 0.f ? c0 + 1.f : expf(c0)) * mv0;
                c1 = (c1 > 0.f ? c1 + 1.f : expf(c1)) * mv0;
                c2 = (c2 > 0.f ? c2 + 1.f : expf(c2)) * mv1;
                c3 = (c3 > 0.f ? c3 + 1.f : expf(c3)) * mv1;
                float k0 = ksp[d], k1 = ksp[d + 1];
                p0 += c0 * k0 + c1 * k1;
                p1 += c2 * k0 + c3 * k1;
                cb[ni][0] = c0; cb[ni][1] = c1; cb[ni][2] = c2; cb[ni][3] = c3;
            }
            p0 += __shfl_xor_sync(0xffffffffu, p0, 1);
            p0 += __shfl_xor_sync(0xffffffffu, p0, 2);
            p1 += __shfl_xor_sync(0xffffffffu, p1, 1);
            p1 += __shfl_xor_sync(0xffffffffu, p1, 2);
            float z0 = 1.f / (p0 + EPSV), z1 = 1.f / (p1 + EPSV);
            int lr0 = wm * 32 + mi * 16 + g, lr1 = lr0 + 8;
#pragma unroll
            for (int ni = 0; ni < 4; ni++) {
                int col = bn + wn * 32 + ni * 8 + tc * 2;
                int kcb = col >> 6, cc = col & 63;
                uint2 s0 = splitpack(cb[ni][0] * z0, cb[ni][1] * z0);
                uint2 s1 = splitpack(cb[ni][2] * z1, cb[ni][3] * z1);
                ushortT* base = g_Qsp + (size_t)rbblk * 73728 + kcb * 18432 + cc;
                *(unsigned*)(base + lr0 * 72) = s0.x;
                *(unsigned*)(base + lr0 * 72 + 9216) = s0.y;
                *(unsigned*)(base + lr1 * 72) = s1.x;
                *(unsigned*)(base + lr1 * 72 + 9216) = s1.y;
            }
        }
    } else {
        // EPI_FEAT (K) / EPI_VPROJ (V): write split-bf16 per-head planes
        int n = bm >> 12;
        int h = (bn >> 5) + wn;          // head = column/32 (FIXED: was bn*4+wn)
        size_t rbase = ((size_t)(n * HH + h) * SS + (bm & (LL - 1)));
        ushortT* Hp = (epi == EPI_FEAT) ? g_Ksp_hi : g_Vsp_hi;
        ushortT* Lp = (epi == EPI_FEAT) ? g_Ksp_lo : g_Vsp_lo;
#pragma unroll
        for (int mi = 0; mi < 2; mi++) {
            int lr0 = wm * 32 + mi * 16 + g, lr1 = lr0 + 8;
            int r0 = bm + lr0, r1 = bm + lr1;
            float mv0 = mask_val(mask, r0), mv1 = mask_val(mask, r1);
#pragma unroll
            for (int ni = 0; ni < 4; ni++) {
                int col = ni * 8 + tc * 2;
                int gcol = bn + wn * 32 + col;
                float c0 = acc[mi][ni][0], c1 = acc[mi][ni][1];
                float c2 = acc[mi][ni][2], c3 = acc[mi][ni][3];
                float b0 = bias[gcol], b1 = bias[gcol + 1];
                if (epi == EPI_FEAT) {
                    c0 += b0; c1 += b1; c2 += b0; c3 += b1;
                    c0 = (c0 > 0.f ? c0 + 1.f : expf(c0)) * mv0;
                    c1 = (c1 > 0.f ? c1 + 1.f : expf(c1)) * mv0;
                    c2 = (c2 > 0.f ? c2 + 1.f : expf(c2)) * mv1;
                    c3 = (c3 > 0.f ? c3 + 1.f : expf(c3)) * mv1;
                } else {
                    c0 = (c0 + b0) * mv0 * scale; c1 = (c1 + b1) * mv0 * scale;
                    c2 = (c2 + b0) * mv1 * scale; c3 = (c3 + b1) * mv1 * scale;
                }
                uint2 s0 = splitpack(c0, c1);
                uint2 s1 = splitpack(c2, c3);
                *(unsigned*)(Hp + (rbase + lr0) * KVP_PITCH + col) = s0.x;
                *(unsigned*)(Lp + (rbase + lr0) * KVP_PITCH + col) = s0.y;
                *(unsigned*)(Hp + (rbase + lr1) * KVP_PITCH + col) = s1.x;
                *(unsigned*)(Lp + (rbase + lr1) * KVP_PITCH + col) = s1.y;
            }
        }
    }
#undef ISSUE_B
#undef LOAD_A
#undef STORE_A
}

// ================= final GEMM: both operands pre-split (pure cp.async + mma) =================
#define PSTAGE 36864                 // hi|lo per chunk
#define SMEM_PRE (4*PSTAGE)          // A x2 stages + B x2 stages = 147456

__global__ void __launch_bounds__(512) tgemm_pre(float* __restrict__ C) {
    uint32_t AsU = smem_u32(dyn_smem);
    uint32_t BsU = AsU + 2 * PSTAGE;

    int tid = threadIdx.x, wid = tid >> 5, lane = tid & 31;
    int wm = wid >> 2, wn = wid & 3;
    int bm = blockIdx.y * 128, bn = blockIdx.x * 128;
    const ushortT* A = g_Qsp + (size_t)(bm >> 7) * 73728;
    const ushortT* B = g_UTsp + (size_t)(bm >> 12) * MATU;

    int lmat = lane >> 3, lrow = lane & 7;
    int a_roff = ((lmat & 1) ? 8 : 0) + lrow;
    int a_coff = (lmat & 2) ? 16 : 0;
    int b_roff = ((lmat & 2) ? 8 : 0) + lrow;
    int b_coff = (lmat & 1) ? 16 : 0;

    float acc[2][4][4];
#pragma unroll
    for (int mi = 0; mi < 2; mi++)
#pragma unroll
        for (int ni = 0; ni < 4; ni++)
#pragma unroll
            for (int j = 0; j < 4; j++) acc[mi][ni][j] = 0.f;

#define ISSUE2(kc, st) do { \
        const char* _as = (const char*)(A + (size_t)(kc) * 18432); \
        const char* _bs = (const char*)(B + (size_t)(blockIdx.x * 4 + (kc)) * 18432); \
        uint32_t _ad = AsU + (st) * PSTAGE, _bd = BsU + (st) * PSTAGE; \
        _Pragma("unroll") \
        for (int _j = 0; _j < 5; _j++) { \
            int _id = tid + _j * 512; \
            if (_id < 2304) { \
                asm volatile("cp.async.cg.shared.global [%0], [%1], 16;" \
                    :: "r"(_ad + _id * 16), "l"(_as + _id * 16)); \
                asm volatile("cp.async.cg.shared.global [%0], [%1], 16;" \
                    :: "r"(_bd + _id * 16), "l"(_bs + _id * 16)); \
            } \
        } \
        asm volatile("cp.async.commit_group;" ::: "memory"); \
    } while (0)

    ISSUE2(0, 0);
    ISSUE2(1, 1);

    for (int kc = 0; kc < 4; kc++) {
        int st = kc & 1;
        if (kc == 3) asm volatile("cp.async.wait_group 0;" ::: "memory");
        else         asm volatile("cp.async.wait_group 1;" ::: "memory");
        __syncthreads();
        uint32_t AhU = AsU + st * PSTAGE, AlU = AhU + TILEB;
        uint32_t BhU = BsU + st * PSTAGE, BlU = BhU + TILEB;
#pragma unroll
        for (int ks = 0; ks < 4; ks++) {
            int cbb = ks * 32;
            unsigned ah[2][4], bh[4][2], bx[4][2], tmp[4];
#pragma unroll
            for (int mi = 0; mi < 2; mi++) {
                int rb = wm * 32 + mi * 16;
                ldsm4(ah[mi], AhU + (rb + a_roff) * PITCHB + cbb + a_coff);
            }
#pragma unroll
            for (int p = 0; p < 2; p++) {
                int nb = wn * 32 + p * 16;
                ldsm4(tmp, BhU + (nb + b_roff) * PITCHB + cbb + b_coff);
                bh[2*p][0] = tmp[0]; bh[2*p][1] = tmp[1];
                bh[2*p+1][0] = tmp[2]; bh[2*p+1][1] = tmp[3];
            }
#pragma unroll
            for (int mi = 0; mi < 2; mi++)
#pragma unroll
                for (int ni = 0; ni < 4; ni++) mma16816(acc[mi][ni], ah[mi], bh[ni]);
#pragma unroll
            for (int p = 0; p < 2; p++) {
                int nb = wn * 32 + p * 16;
                ldsm4(tmp, BlU + (nb + b_roff) * PITCHB + cbb + b_coff);
                bx[2*p][0] = tmp[0]; bx[2*p][1] = tmp[1];
                bx[2*p+1][0] = tmp[2]; bx[2*p+1][1] = tmp[3];
            }
#pragma unroll
            for (int mi = 0; mi < 2; mi++)
#pragma unroll
                for (int ni = 0; ni < 4; ni++) mma16816(acc[mi][ni], ah[mi], bx[ni]);
#pragma unroll
            for (int mi = 0; mi < 2; mi++) {
                int rb = wm * 32 + mi * 16;
                ldsm4(ah[mi], AlU + (rb + a_roff) * PITCHB + cbb + a_coff);
            }
#pragma unroll
            for (int mi = 0; mi < 2; mi++)
#pragma unroll
                for (int ni = 0; ni < 4; ni++) mma16816(acc[mi][ni], ah[mi], bh[ni]);
        }
        __syncthreads();
        if (kc < 2) ISSUE2(kc + 2, st);
    }

    int g = lane >> 2, tc = lane & 3;
#pragma unroll
    for (int mi = 0; mi < 2; mi++) {
        int r0 = bm + wm * 32 + mi * 16 + g;
        int r1 = r0 + 8;
#pragma unroll
        for (int ni = 0; ni < 4; ni++) {
            int col = bn + wn * 32 + ni * 8 + tc * 2;
            *(float2*)&C[(size_t)r0 * EE + col] = make_float2(acc[mi][ni][0], acc[mi][ni][1]);
            *(float2*)&C[(size_t)r1 * EE + col] = make_float2(acc[mi][ni][2], acc[mi][ni][3]);
        }
    }
#undef ISSUE2
}

// ================= KV aggregation via mma: KV[d,v] = sum_s Kf[s,d]*Vm[s,v] =================
// grid (64 nh, NCHUNK), block 256 (8 warps: warp = mi(2) x ni(4))
#define KVTILE 10240                 // 128 rows x 80 B
#define KVSTAGE (4*KVTILE)           // Khi, Klo, Vhi, Vlo
#define SMEM_KV (2*KVSTAGE)          // 81920 B

__global__ void __launch_bounds__(256) kv_mma() {
    int nh = blockIdx.x;
    int chunk = blockIdx.y;
    uint32_t sb = smem_u32(dyn_smem);

    int tid = threadIdx.x, wid = tid >> 5, lane = tid & 31;
    int mi = wid & 1, ni = wid >> 1;
    int lmat = lane >> 3, lrow = lane & 7;
    int g = lane >> 2, tc = lane & 3;

    float acc[4] = {0.f, 0.f, 0.f, 0.f};
    float ksacc[4] = {0.f, 0.f, 0.f, 0.f};
    unsigned ones[2] = {0x3F803F80u, 0x3F803F80u};

#define KVISSUE(sub, st) do { \
        size_t _ro = ((size_t)nh * SS + chunk * CHS + (sub) * 128) * KVP_PITCH; \
        const char* _s0 = (const char*)(g_Ksp_hi + _ro); \
        const char* _s1 = (const char*)(g_Ksp_lo + _ro); \
        const char* _s2 = (const char*)(g_Vsp_hi + _ro); \
        const char* _s3 = (const char*)(g_Vsp_lo + _ro); \
        uint32_t _d = sb + (st) * KVSTAGE; \
        _Pragma("unroll") \
        for (int _j = 0; _j < 3; _j++) { \
            int _id = tid + _j * 256; \
            if (_id < 640) { \
                asm volatile("cp.async.cg.shared.global [%0], [%1], 16;" :: "r"(_d + _id * 16), "l"(_s0 + _id * 16)); \
                asm volatile("cp.async.cg.shared.global [%0], [%1], 16;" :: "r"(_d + KVTILE + _id * 16), "l"(_s1 + _id * 16)); \
                asm volatile("cp.async.cg.shared.global [%0], [%1], 16;" :: "r"(_d + 2 * KVTILE + _id * 16), "l"(_s2 + _id * 16)); \
                asm volatile("cp.async.cg.shared.global [%0], [%1], 16;" :: "r"(_d + 3 * KVTILE + _id * 16), "l"(_s3 + _id * 16)); \
            } \
        } \
        asm volatile("cp.async.commit_group;" ::: "memory"); \
    } while (0)

    KVISSUE(0, 0);
    KVISSUE(1, 1);

    // A-frag (K^T) trans-load offsets: row = k(s), col = m(d)
    int a_row = ((lmat & 2) ? 8 : 0) + lrow;
    int a_col = (mi * 16 + ((lmat & 1) ? 8 : 0)) * 2;   // bytes
    // B-frag (V) trans-load offsets: row = k(s), col = n(v)
    int b_row = ((lane >> 3) & 1) * 8 + (lane & 7);
    int b_col = ni * 8 * 2;                             // bytes

    for (int sub = 0; sub < 4; sub++) {
        int st = sub & 1;
        if (sub == 3) asm volatile("cp.async.wait_group 0;" ::: "memory");
        else          asm volatile("cp.async.wait_group 1;" ::: "memory");
        __syncthreads();
        uint32_t KhU = sb + st * KVSTAGE;
        uint32_t KlU = KhU + KVTILE;
        uint32_t VhU = KhU + 2 * KVTILE;
        uint32_t VlU = KhU + 3 * KVTILE;
#pragma unroll
        for (int ks = 0; ks < 8; ks++) {
            unsigned ah[4], al[4], bh[2], bl[2];
            uint32_t aoff = (ks * 16 + a_row) * 80 + a_col;
            ldsm4t(ah, KhU + aoff);
            ldsm4t(al, KlU + aoff);
            uint32_t boff = (ks * 16 + b_row) * 80 + b_col;
            ldsm2t(bh, VhU + boff);
            ldsm2t(bl, VlU + boff);
            mma16816(acc, ah, bh);
            mma16816(acc, ah, bl);
            mma16816(acc, al, bh);
            if (ni == 0) {
                mma16816(ksacc, ah, ones);
                mma16816(ksacc, al, ones);
            }
        }
        __syncthreads();
        if (sub < 2) KVISSUE(sub + 2, st);
    }

    float* P = g_part + ((size_t)chunk * 64 + nh) * 1056;
    int d0 = mi * 16 + g;
    int v0 = ni * 8 + tc * 2;
    P[d0 * 32 + v0] = acc[0];
    P[d0 * 32 + v0 + 1] = acc[1];
    P[(d0 + 8) * 32 + v0] = acc[2];
    P[(d0 + 8) * 32 + v0 + 1] = acc[3];
    if (ni == 0 && tc == 0) {
        P[1024 + d0] = ksacc[0];
        P[1024 + d0 + 8] = ksacc[2];
    }
#undef KVISSUE
}

// ---------------- fused: reduce partials + write Ksum + emit split-bf16 UT ----------------
__global__ __launch_bounds__(256) void finalize_kv(const float* __restrict__ Wm) {
    int nh = blockIdx.x; int n = nh >> 3, h = nh & 7;
    __shared__ float KVs[32][32];
    int tid = threadIdx.x;
    for (int i = tid; i < 1056; i += 256) {
        float s = 0;
#pragma unroll
        for (int c = 0; c < NCHUNK; c++) s += g_part[((size_t)c * 64 + nh) * 1056 + i];
        if (i < 1024) KVs[i >> 5][i & 31] = s;
        else g_KV[(size_t)nh * 1056 + i] = s;
    }
    __syncthreads();
    int ep = tid;
    float w[32];
#pragma unroll
    for (int v = 0; v < 32; v++) w[v] = Wm[(size_t)ep * EE + h * DD + v];
    ushortT* dsth = g_UTsp + (size_t)n * MATU
                  + ((size_t)((ep >> 7) * 4 + (h >> 1))) * 18432
                  + (ep & 127) * 72 + (h & 1) * 32;
#pragma unroll
    for (int d2 = 0; d2 < 32; d2++) {
        float a = 0;
#pragma unroll
        for (int v = 0; v < 32; v++) a += KVs[d2][v] * w[v];
        a *= (float)SS;
        __nv_bfloat16 hb = __float2bfloat16(a);
        float hr = __bfloat162float(hb);
        __nv_bfloat16 lb = __float2bfloat16(a - hr);
        dsth[d2] = __bfloat16_as_ushort(hb);
        dsth[9216 + d2] = __bfloat16_as_ushort(lb);
    }
}

// ---------------- launch ----------------
extern "C" void kernel_launch(void* const* d_in, const int* in_sizes, int n_in,
                              void* d_out, int out_size) {
    const float* q  = (const float*)d_in[0];
    const float* k  = (const float*)d_in[1];
    const float* v  = (const float*)d_in[2];
    const void*  qm = d_in[3];
    const void*  km = d_in[4];
    const float* Wq = (const float*)d_in[5];
    const float* bq = (const float*)d_in[6];
    const float* Wk = (const float*)d_in[7];
    const float* bk = (const float*)d_in[8];
    const float* Wv = (const float*)d_in[9];
    const float* bv = (const float*)d_in[10];
    const float* Wm = (const float*)d_in[11];
    float* out = (float*)d_out;

    ushortT *Wsp;
    cudaGetSymbolAddress((void**)&Wsp, g_Wsp);

    cudaFuncSetAttribute(tgemm, cudaFuncAttributeMaxDynamicSharedMemorySize, SMEM_SZ);
    cudaFuncSetAttribute(tgemm_pre, cudaFuncAttributeMaxDynamicSharedMemorySize, SMEM_PRE);
    cudaFuncSetAttribute(kv_mma, cudaFuncAttributeMaxDynamicSharedMemorySize, SMEM_KV);

    detect_mask_kernel<<<1, 256>>>((const unsigned int*)km, 2048);
    split_w3<<<dim3(16, 3), 256>>>(Wq, Wk, Wv);

    // K and V projections (fused, z = 2) -> split-bf16 per-head planes
    tgemm<<<dim3(2, NTOK / 128, 2), 512, SMEM_SZ>>>(
        k, v, Wsp + MATU, MATU,
        bk, bv,
        EPI_FEAT, EPI_VPROJ,
        km, 1.f / (float)SS);

    kv_mma<<<dim3(64, NCHUNK), 256, SMEM_KV>>>();
    finalize_kv<<<64, 256>>>(Wm);

    // Q projection with Z folded; writes split-tiled g_Qsp
    tgemm<<<dim3(2, NTOK / 128, 1), 512, SMEM_SZ>>>(
        q, q, Wsp, 0,
        bq, bq,
        EPI_QZ, EPI_QZ,
        qm, 1.f);

    // final: (Qf*Z) @ UT[n]^T, both operands pre-split
    tgemm_pre<<<dim3(2, NTOK / 128), 512, SMEM_PRE>>>(out);
}

// round 13
// speedup vs baseline: 1.4749x; 1.4749x over previous
#include <cuda_runtime.h>
#include <cuda_bf16.h>
#include <cstdint>

#define Nb 8
#define LL 4096
#define SS 4096
#define EE 256
#define HH 8
#define DD 32
#define NTOK (Nb*LL)
#define EPSV 1e-6f
#define NCHUNK 8
#define CHS (SS/NCHUNK)

typedef unsigned short ushortT;

// ---------------- scratch ----------------
__device__ __nv_bfloat16 g_Kf[Nb*SS*EE];   // bf16 feature-mapped K (16 MB)
__device__ __nv_bfloat16 g_Vm[Nb*SS*EE];   // bf16 masked V / S (16 MB)
__device__ float g_part[NCHUNK*Nb*HH*1056];
__device__ float g_KV[Nb*HH*1056];     // only Ksum range [1024..1055] consumed downstream
__device__ int   g_mask_kind;
#define MATU 147456                    // ushorts per 256x256 split matrix
__device__ ushortT g_Wsp[3*MATU];      // Wq, Wk, Wv  (tiled hi/lo bf16)
__device__ ushortT g_UTsp[Nb*MATU];    // per-batch UT (tiled hi/lo bf16)
// Qf*Z, split-tiled: 256 row-blocks x (4 kc x (hi 9216 | lo 9216)) ushorts
__device__ ushortT g_Qsp[(NTOK/128)*73728];

// ---------------- helpers ----------------
__device__ __forceinline__ uint32_t smem_u32(const void* p) {
    uint32_t a;
    asm("{ .reg .u64 t; cvta.to.shared.u64 t, %1; cvt.u32.u64 %0, t; }" : "=r"(a) : "l"(p));
    return a;
}
__device__ __forceinline__ void ldsm4(unsigned* r, uint32_t addr) {
    asm volatile("ldmatrix.sync.aligned.m8n8.x4.shared.b16 {%0,%1,%2,%3}, [%4];"
        : "=r"(r[0]), "=r"(r[1]), "=r"(r[2]), "=r"(r[3]) : "r"(addr));
}
__device__ __forceinline__ void mma16816(float* c, const unsigned* a, const unsigned* b) {
    asm volatile("mma.sync.aligned.m16n8k16.row.col.f32.bf16.bf16.f32 "
        "{%0,%1,%2,%3}, {%4,%5,%6,%7}, {%8,%9}, {%0,%1,%2,%3};"
        : "+f"(c[0]), "+f"(c[1]), "+f"(c[2]), "+f"(c[3])
        : "r"(a[0]), "r"(a[1]), "r"(a[2]), "r"(a[3]), "r"(b[0]), "r"(b[1]));
}
__device__ __forceinline__ uint2 splitpack(float x0, float x1) {
    __nv_bfloat162 h = __float22bfloat162_rn(make_float2(x0, x1));
    float2 hf = __bfloat1622float2(h);
    __nv_bfloat162 l = __float22bfloat162_rn(make_float2(x0 - hf.x, x1 - hf.y));
    uint2 o;
    o.x = *(unsigned*)&h;
    o.y = *(unsigned*)&l;
    return o;
}

// ---------------- mask dtype detection ----------------
__global__ void detect_mask_kernel(const unsigned int* __restrict__ m, int nwords) {
    __shared__ int flags[3];
    if (threadIdx.x < 3) flags[threadIdx.x] = 0;
    __syncthreads();
    for (int i = threadIdx.x; i < nwords; i += blockDim.x) {
        unsigned w = m[i];
        if (w == 0x3F803F80u || w == 0x00003F80u) atomicOr(&flags[0], 1);
        else if (w == 0x3F800000u) atomicOr(&flags[1], 1);
        else if (w > 1u) {
            unsigned b0 = w & 255u, b1 = (w >> 8) & 255u, b2 = (w >> 16) & 255u, b3 = w >> 24;
            if (b0 <= 1u && b1 <= 1u && b2 <= 1u && b3 <= 1u) atomicOr(&flags[2], 1);
        }
    }
    __syncthreads();
    if (threadIdx.x == 0) {
        int kind;
        if (flags[0]) kind = 3;
        else if (flags[1]) kind = 2;
        else if (flags[2]) kind = 0;
        else kind = 1;
        g_mask_kind = kind;
    }
}

__device__ __forceinline__ float mask_val(const void* p, int i) {
    int k = g_mask_kind;
    if (k == 0) return ((const unsigned char*)p)[i] ? 1.f : 0.f;
    if (k == 1) return ((const int*)p)[i] ? 1.f : 0.f;
    if (k == 2) return ((const float*)p)[i];
    return __bfloat162float(((const __nv_bfloat16*)p)[i]);
}

// ---------------- pre-split the 3 weight matrices (48 blocks) ----------------
__global__ __launch_bounds__(256) void split_w3(const float* __restrict__ W0,
                                                const float* __restrict__ W1,
                                                const float* __restrict__ W2) {
    int y = blockIdx.y;
    const float* src = y == 0 ? W0 : (y == 1 ? W1 : W2);
    ushortT* dst = g_Wsp + (size_t)y * MATU;
    int blk = blockIdx.x >> 1;       // 0..7 = nh2*4 + kc
    int half = blockIdx.x & 1;       // 64-row half
    int nh2 = blk >> 2, kc = blk & 3;
    int tid = threadIdx.x;
    size_t ubase = (size_t)blk * 18432;
#pragma unroll
    for (int i = 0; i < 4; i++) {
        int idx = tid + i * 256;
        int r = half * 64 + (idx >> 4), c4 = (idx & 15) * 4;
        float4 v = *(const float4*)&src[(size_t)(nh2 * 128 + r) * EE + kc * 64 + c4];
        uint2 s0 = splitpack(v.x, v.y);
        uint2 s1 = splitpack(v.z, v.w);
        ushortT* hp = dst + ubase + r * 72 + c4;
        *(unsigned*)hp = s0.x; *(unsigned*)(hp + 2) = s1.x;
        ushortT* lp = hp + 9216;
        *(unsigned*)lp = s0.y; *(unsigned*)(lp + 2) = s1.y;
    }
}

// ================= pipelined mma.sync split-bf16 GEMM (projections) =================
#define EPI_FEAT  1   // elu+1, mask -> bf16 C
#define EPI_VPROJ 2   // (x+b)*mask*scale -> bf16 C
#define EPI_QZ    3   // elu+1, mask, fold Z, write split-tiled g_Qsp
#define PITCHB 144
#define TILEB (128*PITCHB)    // 18432 B
#define BSTAGE (2*TILEB)
#define SMEM_SZ (2*TILEB + 2*BSTAGE)   // 110592 B

extern __shared__ char dyn_smem[];

__global__ void __launch_bounds__(512, 2) tgemm(
    const float* __restrict__ A0, const float* __restrict__ A1,
    const ushortT* __restrict__ Bsp, int bStrideZ,
    const float* __restrict__ bias0, const float* __restrict__ bias1,
    void* __restrict__ C0, void* __restrict__ C1,
    int epi0, int epi1,
    const void* __restrict__ mask, float scale)
{
    int z = blockIdx.z;
    const float* A    = z == 0 ? A0 : A1;
    const float* bias = z == 0 ? bias0 : bias1;
    void* C           = z == 0 ? C0 : C1;
    int epi           = z == 0 ? epi0 : epi1;

    uint32_t AhU = smem_u32(dyn_smem);
    uint32_t AlU = AhU + TILEB;
    uint32_t BsU = AhU + 2 * TILEB;

    int tid = threadIdx.x, wid = tid >> 5, lane = tid & 31;
    int wm = wid >> 2, wn = wid & 3;
    int bm = blockIdx.y * 128, bn = blockIdx.x * 128;
    const ushortT* B = Bsp + (size_t)z * bStrideZ;

    int lmat = lane >> 3, lrow = lane & 7;
    int a_roff = ((lmat & 1) ? 8 : 0) + lrow;
    int a_coff = (lmat & 2) ? 16 : 0;
    int b_roff = ((lmat & 2) ? 8 : 0) + lrow;
    int b_coff = (lmat & 1) ? 16 : 0;

    float acc[2][4][4];
#pragma unroll
    for (int mi = 0; mi < 2; mi++)
#pragma unroll
        for (int ni = 0; ni < 4; ni++)
#pragma unroll
            for (int j = 0; j < 4; j++) acc[mi][ni][j] = 0.f;

    float4 pf[4];

#define ISSUE_B(kc, stage) do { \
        const char* _src = (const char*)(B + (size_t)(blockIdx.x * 4 + (kc)) * 18432); \
        uint32_t _db = BsU + (stage) * BSTAGE; \
        _Pragma("unroll") \
        for (int _j = 0; _j < 5; _j++) { \
            int _id = tid + _j * 512; \
            if (_id < 2304) \
                asm volatile("cp.async.cg.shared.global [%0], [%1], 16;" \
                    :: "r"(_db + _id * 16), "l"(_src + _id * 16)); \
        } \
        asm volatile("cp.async.commit_group;" ::: "memory"); \
    } while (0)

#define LOAD_A(kc) do { \
        _Pragma("unroll") \
        for (int _i = 0; _i < 4; _i++) { \
            int _idx = tid + _i * 512; \
            int _r = _idx >> 4, _c4 = (_idx & 15) << 2; \
            pf[_i] = *(const float4*)&A[(size_t)(bm + _r) * EE + (kc) * 64 + _c4]; \
        } \
    } while (0)

#define STORE_A() do { \
        _Pragma("unroll") \
        for (int _i = 0; _i < 4; _i++) { \
            int _idx = tid + _i * 512; \
            int _r = _idx >> 4, _c4 = (_idx & 15) << 2; \
            uint32_t _off = _r * PITCHB + _c4 * 2; \
            uint2 _s0 = splitpack(pf[_i].x, pf[_i].y); \
            uint2 _s1 = splitpack(pf[_i].z, pf[_i].w); \
            asm volatile("st.shared.v2.b32 [%0], {%1,%2};" :: "r"(AhU + _off), "r"(_s0.x), "r"(_s1.x) : "memory"); \
            asm volatile("st.shared.v2.b32 [%0], {%1,%2};" :: "r"(AlU + _off), "r"(_s0.y), "r"(_s1.y) : "memory"); \
        } \
    } while (0)

    ISSUE_B(0, 0);
    LOAD_A(0);
    STORE_A();
    asm volatile("cp.async.wait_group 0;" ::: "memory");
    __syncthreads();

    for (int kc = 0; kc < 4; kc++) {
        int s = kc & 1;
        if (kc < 3) {
            ISSUE_B(kc + 1, s ^ 1);
            LOAD_A(kc + 1);
        }
        uint32_t BhU = BsU + s * BSTAGE;
        uint32_t BlU = BhU + TILEB;
#pragma unroll
        for (int ks = 0; ks < 4; ks++) {
            int cbb = ks * 32;
            unsigned ah[2][4], bh[4][2], bx[4][2], tmp[4];
#pragma unroll
            for (int mi = 0; mi < 2; mi++) {
                int rb = wm * 32 + mi * 16;
                ldsm4(ah[mi], AhU + (rb + a_roff) * PITCHB + cbb + a_coff);
            }
#pragma unroll
            for (int p = 0; p < 2; p++) {
                int nb = wn * 32 + p * 16;
                ldsm4(tmp, BhU + (nb + b_roff) * PITCHB + cbb + b_coff);
                bh[2*p][0] = tmp[0]; bh[2*p][1] = tmp[1];
                bh[2*p+1][0] = tmp[2]; bh[2*p+1][1] = tmp[3];
            }
#pragma unroll
            for (int mi = 0; mi < 2; mi++)
#pragma unroll
                for (int ni = 0; ni < 4; ni++) mma16816(acc[mi][ni], ah[mi], bh[ni]);
#pragma unroll
            for (int p = 0; p < 2; p++) {
                int nb = wn * 32 + p * 16;
                ldsm4(tmp, BlU + (nb + b_roff) * PITCHB + cbb + b_coff);
                bx[2*p][0] = tmp[0]; bx[2*p][1] = tmp[1];
                bx[2*p+1][0] = tmp[2]; bx[2*p+1][1] = tmp[3];
            }
#pragma unroll
            for (int mi = 0; mi < 2; mi++)
#pragma unroll
                for (int ni = 0; ni < 4; ni++) mma16816(acc[mi][ni], ah[mi], bx[ni]);
#pragma unroll
            for (int mi = 0; mi < 2; mi++) {
                int rb = wm * 32 + mi * 16;
                ldsm4(ah[mi], AlU + (rb + a_roff) * PITCHB + cbb + a_coff);
            }
#pragma unroll
            for (int mi = 0; mi < 2; mi++)
#pragma unroll
                for (int ni = 0; ni < 4; ni++) mma16816(acc[mi][ni], ah[mi], bh[ni]);
        }
        __syncthreads();
        if (kc < 3) {
            STORE_A();
            asm volatile("cp.async.wait_group 0;" ::: "memory");
            __syncthreads();
        }
    }

    // ---- epilogue ----
    int g = lane >> 2, tc = lane & 3;
    if (epi == EPI_QZ) {
        int n = bm >> 12;
        int h = (bn + wn * 32) >> 5;
        const float* ksp = g_KV + (size_t)(n * HH + h) * 1056 + 1024;
        int rbblk = bm >> 7;
#pragma unroll
        for (int mi = 0; mi < 2; mi++) {
            int r0 = bm + wm * 32 + mi * 16 + g;
            int r1 = r0 + 8;
            float mv0 = mask_val(mask, r0), mv1 = mask_val(mask, r1);
            float cb[4][4];
            float p0 = 0.f, p1 = 0.f;
#pragma unroll
            for (int ni = 0; ni < 4; ni++) {
                int col = bn + wn * 32 + ni * 8 + tc * 2;
                int d = ni * 8 + tc * 2;
                float b0 = bias[col], b1 = bias[col + 1];
                float c0 = acc[mi][ni][0] + b0, c1 = acc[mi][ni][1] + b1;
                float c2 = acc[mi][ni][2] + b0, c3 = acc[mi][ni][3] + b1;
                c0 = (c0 > 0.f ? c0 + 1.f : expf(c0)) * mv0;
                c1 = (c1 > 0.f ? c1 + 1.f : expf(c1)) * mv0;
                c2 = (c2 > 0.f ? c2 + 1.f : expf(c2)) * mv1;
                c3 = (c3 > 0.f ? c3 + 1.f : expf(c3)) * mv1;
                float k0 = ksp[d], k1 = ksp[d + 1];
                p0 += c0 * k0 + c1 * k1;
                p1 += c2 * k0 + c3 * k1;
                cb[ni][0] = c0; cb[ni][1] = c1; cb[ni][2] = c2; cb[ni][3] = c3;
            }
            p0 += __shfl_xor_sync(0xffffffffu, p0, 1);
            p0 += __shfl_xor_sync(0xffffffffu, p0, 2);
            p1 += __shfl_xor_sync(0xffffffffu, p1, 1);
            p1 += __shfl_xor_sync(0xffffffffu, p1, 2);
            float z0 = 1.f / (p0 + EPSV), z1 = 1.f / (p1 + EPSV);
            int lr0 = wm * 32 + mi * 16 + g, lr1 = lr0 + 8;
#pragma unroll
            for (int ni = 0; ni < 4; ni++) {
                int col = bn + wn * 32 + ni * 8 + tc * 2;
                int kcb = col >> 6, cc = col & 63;
                uint2 s0 = splitpack(cb[ni][0] * z0, cb[ni][1] * z0);
                uint2 s1 = splitpack(cb[ni][2] * z1, cb[ni][3] * z1);
                ushortT* base = g_Qsp + (size_t)rbblk * 73728 + kcb * 18432 + cc;
                *(unsigned*)(base + lr0 * 72) = s0.x;
                *(unsigned*)(base + lr0 * 72 + 9216) = s0.y;
                *(unsigned*)(base + lr1 * 72) = s1.x;
                *(unsigned*)(base + lr1 * 72 + 9216) = s1.y;
            }
        }
    } else {
        // EPI_FEAT / EPI_VPROJ -> bf16 row-major output (coalesced 4B stores)
        __nv_bfloat16* Cb = (__nv_bfloat16*)C;
#pragma unroll
        for (int mi = 0; mi < 2; mi++) {
            int r0 = bm + wm * 32 + mi * 16 + g;
            int r1 = r0 + 8;
            float mv0 = mask_val(mask, r0), mv1 = mask_val(mask, r1);
#pragma unroll
            for (int ni = 0; ni < 4; ni++) {
                int col = bn + wn * 32 + ni * 8 + tc * 2;
                float c0 = acc[mi][ni][0], c1 = acc[mi][ni][1];
                float c2 = acc[mi][ni][2], c3 = acc[mi][ni][3];
                float b0 = bias[col], b1 = bias[col + 1];
                if (epi == EPI_FEAT) {
                    c0 += b0; c1 += b1; c2 += b0; c3 += b1;
                    c0 = (c0 > 0.f ? c0 + 1.f : expf(c0)) * mv0;
                    c1 = (c1 > 0.f ? c1 + 1.f : expf(c1)) * mv0;
                    c2 = (c2 > 0.f ? c2 + 1.f : expf(c2)) * mv1;
                    c3 = (c3 > 0.f ? c3 + 1.f : expf(c3)) * mv1;
                } else {  // EPI_VPROJ
                    c0 = (c0 + b0) * mv0 * scale; c1 = (c1 + b1) * mv0 * scale;
                    c2 = (c2 + b0) * mv1 * scale; c3 = (c3 + b1) * mv1 * scale;
                }
                *(__nv_bfloat162*)&Cb[(size_t)r0 * EE + col] =
                    __float22bfloat162_rn(make_float2(c0, c1));
                *(__nv_bfloat162*)&Cb[(size_t)r1 * EE + col] =
                    __float22bfloat162_rn(make_float2(c2, c3));
            }
        }
    }
#undef ISSUE_B
#undef LOAD_A
#undef STORE_A
}

// ================= final GEMM: both operands pre-split (pure cp.async + mma) =================
#define PSTAGE 36864                 // hi|lo per chunk
#define SMEM_PRE (4*PSTAGE)          // A x2 stages + B x2 stages = 147456

__global__ void __launch_bounds__(512) tgemm_pre(float* __restrict__ C) {
    uint32_t AsU = smem_u32(dyn_smem);
    uint32_t BsU = AsU + 2 * PSTAGE;

    int tid = threadIdx.x, wid = tid >> 5, lane = tid & 31;
    int wm = wid >> 2, wn = wid & 3;
    int bm = blockIdx.y * 128, bn = blockIdx.x * 128;
    const ushortT* A = g_Qsp + (size_t)(bm >> 7) * 73728;
    const ushortT* B = g_UTsp + (size_t)(bm >> 12) * MATU;

    int lmat = lane >> 3, lrow = lane & 7;
    int a_roff = ((lmat & 1) ? 8 : 0) + lrow;
    int a_coff = (lmat & 2) ? 16 : 0;
    int b_roff = ((lmat & 2) ? 8 : 0) + lrow;
    int b_coff = (lmat & 1) ? 16 : 0;

    float acc[2][4][4];
#pragma unroll
    for (int mi = 0; mi < 2; mi++)
#pragma unroll
        for (int ni = 0; ni < 4; ni++)
#pragma unroll
            for (int j = 0; j < 4; j++) acc[mi][ni][j] = 0.f;

#define ISSUE2(kc, st) do { \
        const char* _as = (const char*)(A + (size_t)(kc) * 18432); \
        const char* _bs = (const char*)(B + (size_t)(blockIdx.x * 4 + (kc)) * 18432); \
        uint32_t _ad = AsU + (st) * PSTAGE, _bd = BsU + (st) * PSTAGE; \
        _Pragma("unroll") \
        for (int _j = 0; _j < 5; _j++) { \
            int _id = tid + _j * 512; \
            if (_id < 2304) { \
                asm volatile("cp.async.cg.shared.global [%0], [%1], 16;" \
                    :: "r"(_ad + _id * 16), "l"(_as + _id * 16)); \
                asm volatile("cp.async.cg.shared.global [%0], [%1], 16;" \
                    :: "r"(_bd + _id * 16), "l"(_bs + _id * 16)); \
            } \
        } \
        asm volatile("cp.async.commit_group;" ::: "memory"); \
    } while (0)

    ISSUE2(0, 0);
    ISSUE2(1, 1);

    for (int kc = 0; kc < 4; kc++) {
        int st = kc & 1;
        if (kc == 3) asm volatile("cp.async.wait_group 0;" ::: "memory");
        else         asm volatile("cp.async.wait_group 1;" ::: "memory");
        __syncthreads();
        uint32_t AhU = AsU + st * PSTAGE, AlU = AhU + TILEB;
        uint32_t BhU = BsU + st * PSTAGE, BlU = BhU + TILEB;
#pragma unroll
        for (int ks = 0; ks < 4; ks++) {
            int cbb = ks * 32;
            unsigned ah[2][4], bh[4][2], bx[4][2], tmp[4];
#pragma unroll
            for (int mi = 0; mi < 2; mi++) {
                int rb = wm * 32 + mi * 16;
                ldsm4(ah[mi], AhU + (rb + a_roff) * PITCHB + cbb + a_coff);
            }
#pragma unroll
            for (int p = 0; p < 2; p++) {
                int nb = wn * 32 + p * 16;
                ldsm4(tmp, BhU + (nb + b_roff) * PITCHB + cbb + b_coff);
                bh[2*p][0] = tmp[0]; bh[2*p][1] = tmp[1];
                bh[2*p+1][0] = tmp[2]; bh[2*p+1][1] = tmp[3];
            }
#pragma unroll
            for (int mi = 0; mi < 2; mi++)
#pragma unroll
                for (int ni = 0; ni < 4; ni++) mma16816(acc[mi][ni], ah[mi], bh[ni]);
#pragma unroll
            for (int p = 0; p < 2; p++) {
                int nb = wn * 32 + p * 16;
                ldsm4(tmp, BlU + (nb + b_roff) * PITCHB + cbb + b_coff);
                bx[2*p][0] = tmp[0]; bx[2*p][1] = tmp[1];
                bx[2*p+1][0] = tmp[2]; bx[2*p+1][1] = tmp[3];
            }
#pragma unroll
            for (int mi = 0; mi < 2; mi++)
#pragma unroll
                for (int ni = 0; ni < 4; ni++) mma16816(acc[mi][ni], ah[mi], bx[ni]);
#pragma unroll
            for (int mi = 0; mi < 2; mi++) {
                int rb = wm * 32 + mi * 16;
                ldsm4(ah[mi], AlU + (rb + a_roff) * PITCHB + cbb + a_coff);
            }
#pragma unroll
            for (int mi = 0; mi < 2; mi++)
#pragma unroll
                for (int ni = 0; ni < 4; ni++) mma16816(acc[mi][ni], ah[mi], bh[ni]);
        }
        __syncthreads();
        if (kc < 2) ISSUE2(kc + 2, st);
    }

    int g = lane >> 2, tc = lane & 3;
#pragma unroll
    for (int mi = 0; mi < 2; mi++) {
        int r0 = bm + wm * 32 + mi * 16 + g;
        int r1 = r0 + 8;
#pragma unroll
        for (int ni = 0; ni < 4; ni++) {
            int col = bn + wn * 32 + ni * 8 + tc * 2;
            *(float2*)&C[(size_t)r0 * EE + col] = make_float2(acc[mi][ni][0], acc[mi][ni][1]);
            *(float2*)&C[(size_t)r1 * EE + col] = make_float2(acc[mi][ni][2], acc[mi][ni][3]);
        }
    }
#undef ISSUE2
}

// ---------------- KV aggregation: register-tiled partial sums (bf16 input) ----------------
__global__ __launch_bounds__(256) void kv_partial() {
    int nh = blockIdx.x;
    int n = nh >> 3, h = nh & 7;
    int chunk = blockIdx.y;
    __shared__ float Ks[64][32];
    __shared__ float Vs[64][32];
    __shared__ float red[4][1056];
    int tid = threadIdx.x;
    int grp = tid >> 6;
    int gt = tid & 63;
    int dg = gt >> 3;
    int vg = gt & 7;
    float acc[4][4] = {};
    float ks[4] = {};
    int s0base = chunk * CHS;
    const __nv_bfloat16* Kp = g_Kf + (size_t)n * SS * EE + h * DD;
    const __nv_bfloat16* Vp = g_Vm + (size_t)n * SS * EE + h * DD;
    for (int s0 = 0; s0 < CHS; s0 += 64) {
#pragma unroll
        for (int r = 0; r < 2; r++) {
            int idx = tid + r * 256;
            int row = idx >> 3, c = (idx & 7) * 4;
            size_t gidx = (size_t)(s0base + s0 + row) * EE + c;
            uint2 kk = *(const uint2*)&Kp[gidx];
            float2 kf0 = __bfloat1622float2(*(__nv_bfloat162*)&kk.x);
            float2 kf1 = __bfloat1622float2(*(__nv_bfloat162*)&kk.y);
            *(float4*)&Ks[row][c] = make_float4(kf0.x, kf0.y, kf1.x, kf1.y);
            uint2 vv = *(const uint2*)&Vp[gidx];
            float2 vf0 = __bfloat1622float2(*(__nv_bfloat162*)&vv.x);
            float2 vf1 = __bfloat1622float2(*(__nv_bfloat162*)&vv.y);
            *(float4*)&Vs[row][c] = make_float4(vf0.x, vf0.y, vf1.x, vf1.y);
        }
        __syncthreads();
#pragma unroll
        for (int si = 0; si < 16; si++) {
            int s = grp * 16 + si;
            float4 kk = *(const float4*)&Ks[s][dg * 4];
            float4 vv = *(const float4*)&Vs[s][vg * 4];
            float ka[4] = {kk.x, kk.y, kk.z, kk.w};
            float va[4] = {vv.x, vv.y, vv.z, vv.w};
#pragma unroll
            for (int i = 0; i < 4; i++) {
                ks[i] += ka[i];
#pragma unroll
                for (int j = 0; j < 4; j++) acc[i][j] += ka[i] * va[j];
            }
        }
        __syncthreads();
    }
#pragma unroll
    for (int i = 0; i < 4; i++)
#pragma unroll
        for (int j = 0; j < 4; j++)
            red[grp][(dg * 4 + i) * 32 + vg * 4 + j] = acc[i][j];
    if (vg == 0) {
#pragma unroll
        for (int i = 0; i < 4; i++) red[grp][1024 + dg * 4 + i] = ks[i];
    }
    __syncthreads();
    float* P = g_part + ((size_t)chunk * 64 + nh) * 1056;
    for (int i = tid; i < 1056; i += 256)
        P[i] = red[0][i] + red[1][i] + red[2][i] + red[3][i];
}

// ---------------- fused: reduce partials + write Ksum + emit split-bf16 UT ----------------
__global__ __launch_bounds__(256) void finalize_kv(const float* __restrict__ Wm) {
    int nh = blockIdx.x; int n = nh >> 3, h = nh & 7;
    __shared__ float KVs[32][32];
    int tid = threadIdx.x;
    for (int i = tid; i < 1056; i += 256) {
        float s = 0;
#pragma unroll
        for (int c = 0; c < NCHUNK; c++) s += g_part[((size_t)c * 64 + nh) * 1056 + i];
        if (i < 1024) KVs[i >> 5][i & 31] = s;
        else g_KV[(size_t)nh * 1056 + i] = s;
    }
    __syncthreads();
    int ep = tid;
    float w[32];
#pragma unroll
    for (int v = 0; v < 32; v++) w[v] = Wm[(size_t)ep * EE + h * DD + v];
    ushortT* dsth = g_UTsp + (size_t)n * MATU
                  + ((size_t)((ep >> 7) * 4 + (h >> 1))) * 18432
                  + (ep & 127) * 72 + (h & 1) * 32;
#pragma unroll
    for (int d2 = 0; d2 < 32; d2++) {
        float a = 0;
#pragma unroll
        for (int v = 0; v < 32; v++) a += KVs[d2][v] * w[v];
        a *= (float)SS;
        __nv_bfloat16 hb = __float2bfloat16(a);
        float hr = __bfloat162float(hb);
        __nv_bfloat16 lb = __float2bfloat16(a - hr);
        dsth[d2] = __bfloat16_as_ushort(hb);
        dsth[9216 + d2] = __bfloat16_as_ushort(lb);
    }
}

// ---------------- launch ----------------
extern "C" void kernel_launch(void* const* d_in, const int* in_sizes, int n_in,
                              void* d_out, int out_size) {
    const float* q  = (const float*)d_in[0];
    const float* k  = (const float*)d_in[1];
    const float* v  = (const float*)d_in[2];
    const void*  qm = d_in[3];
    const void*  km = d_in[4];
    const float* Wq = (const float*)d_in[5];
    const float* bq = (const float*)d_in[6];
    const float* Wk = (const float*)d_in[7];
    const float* bk = (const float*)d_in[8];
    const float* Wv = (const float*)d_in[9];
    const float* bv = (const float*)d_in[10];
    const float* Wm = (const float*)d_in[11];
    float* out = (float*)d_out;

    void *Kf, *Vm;
    ushortT *Wsp;
    cudaGetSymbolAddress(&Kf, g_Kf);
    cudaGetSymbolAddress(&Vm, g_Vm);
    cudaGetSymbolAddress((void**)&Wsp, g_Wsp);

    cudaFuncSetAttribute(tgemm, cudaFuncAttributeMaxDynamicSharedMemorySize, SMEM_SZ);
    cudaFuncSetAttribute(tgemm_pre, cudaFuncAttributeMaxDynamicSharedMemorySize, SMEM_PRE);

    detect_mask_kernel<<<1, 256>>>((const unsigned int*)km, 2048);
    split_w3<<<dim3(16, 3), 256>>>(Wq, Wk, Wv);

    // K and V projections (fused, z = 2) -> bf16 row-major Kf/Vm
    tgemm<<<dim3(2, NTOK / 128, 2), 512, SMEM_SZ>>>(
        k, v, Wsp + MATU, MATU,
        bk, bv, Kf, Vm,
        EPI_FEAT, EPI_VPROJ,
        km, 1.f / (float)SS);

    kv_partial<<<dim3(64, NCHUNK), 256>>>();
    finalize_kv<<<64, 256>>>(Wm);

    // Q projection with Z folded; writes split-tiled g_Qsp
    tgemm<<<dim3(2, NTOK / 128, 1), 512, SMEM_SZ>>>(
        q, q, Wsp, 0,
        bq, bq, out, out,
        EPI_QZ, EPI_QZ,
        qm, 1.f);

    // final: (Qf*Z) @ UT[n]^T, both operands pre-split
    tgemm_pre<<<dim3(2, NTOK / 128), 512, SMEM_PRE>>>(out);
}

// round 14
// speedup vs baseline: 1.4804x; 1.0037x over previous
#include <cuda_runtime.h>
#include <cuda_bf16.h>
#include <cstdint>

#define Nb 8
#define LL 4096
#define SS 4096
#define EE 256
#define HH 8
#define DD 32
#define NTOK (Nb*LL)
#define EPSV 1e-6f
#define NCHUNK 8
#define CHS (SS/NCHUNK)

typedef unsigned short ushortT;

// ---------------- scratch ----------------
__device__ float g_Kf[Nb*SS*EE];
__device__ float g_Vm[Nb*SS*EE];
__device__ float g_part[NCHUNK*Nb*HH*1056];
__device__ float g_KV[Nb*HH*1056];     // Ksum at [1024..1055]
__device__ int   g_mask_kind;
#define MATU 147456                    // ushorts per 256x256 split matrix
__device__ ushortT g_Wsp[3*MATU];      // Wq, Wk, Wv  (tiled hi/lo bf16)
__device__ ushortT g_UTsp[Nb*MATU];    // per-batch UT (tiled hi/lo bf16)

// ---------------- helpers ----------------
__device__ __forceinline__ uint32_t smem_u32(const void* p) {
    uint32_t a;
    asm("{ .reg .u64 t; cvta.to.shared.u64 t, %1; cvt.u32.u64 %0, t; }" : "=r"(a) : "l"(p));
    return a;
}
__device__ __forceinline__ void ldsm4(unsigned* r, uint32_t addr) {
    asm volatile("ldmatrix.sync.aligned.m8n8.x4.shared.b16 {%0,%1,%2,%3}, [%4];"
        : "=r"(r[0]), "=r"(r[1]), "=r"(r[2]), "=r"(r[3]) : "r"(addr));
}
__device__ __forceinline__ void mma16816(float* c, const unsigned* a, const unsigned* b) {
    asm volatile("mma.sync.aligned.m16n8k16.row.col.f32.bf16.bf16.f32 "
        "{%0,%1,%2,%3}, {%4,%5,%6,%7}, {%8,%9}, {%0,%1,%2,%3};"
        : "+f"(c[0]), "+f"(c[1]), "+f"(c[2]), "+f"(c[3])
        : "r"(a[0]), "r"(a[1]), "r"(a[2]), "r"(a[3]), "r"(b[0]), "r"(b[1]));
}
__device__ __forceinline__ uint2 splitpack(float x0, float x1) {
    __nv_bfloat162 h = __float22bfloat162_rn(make_float2(x0, x1));
    float2 hf = __bfloat1622float2(h);
    __nv_bfloat162 l = __float22bfloat162_rn(make_float2(x0 - hf.x, x1 - hf.y));
    uint2 o;
    o.x = *(unsigned*)&h;
    o.y = *(unsigned*)&l;
    return o;
}

// ---------------- mask dtype detection ----------------
__global__ void detect_mask_kernel(const unsigned int* __restrict__ m, int nwords) {
    __shared__ int flags[3];
    if (threadIdx.x < 3) flags[threadIdx.x] = 0;
    __syncthreads();
    for (int i = threadIdx.x; i < nwords; i += blockDim.x) {
        unsigned w = m[i];
        if (w == 0x3F803F80u || w == 0x00003F80u) atomicOr(&flags[0], 1);
        else if (w == 0x3F800000u) atomicOr(&flags[1], 1);
        else if (w > 1u) {
            unsigned b0 = w & 255u, b1 = (w >> 8) & 255u, b2 = (w >> 16) & 255u, b3 = w >> 24;
            if (b0 <= 1u && b1 <= 1u && b2 <= 1u && b3 <= 1u) atomicOr(&flags[2], 1);
        }
    }
    __syncthreads();
    if (threadIdx.x == 0) {
        int kind;
        if (flags[0]) kind = 3;
        else if (flags[1]) kind = 2;
        else if (flags[2]) kind = 0;
        else kind = 1;
        g_mask_kind = kind;
    }
}

__device__ __forceinline__ float mask_val(const void* p, int i) {
    int k = g_mask_kind;
    if (k == 0) return ((const unsigned char*)p)[i] ? 1.f : 0.f;
    if (k == 1) return ((const int*)p)[i] ? 1.f : 0.f;
    if (k == 2) return ((const float*)p)[i];
    return __bfloat162float(((const __nv_bfloat16*)p)[i]);
}

// ---------------- pre-split the 3 weight matrices ----------------
__global__ __launch_bounds__(256) void split_w3(const float* __restrict__ W0,
                                                const float* __restrict__ W1,
                                                const float* __restrict__ W2) {
    int y = blockIdx.y;
    const float* src = y == 0 ? W0 : (y == 1 ? W1 : W2);
    ushortT* dst = g_Wsp + (size_t)y * MATU;
    int blk = blockIdx.x >> 1;
    int half = blockIdx.x & 1;
    int nh2 = blk >> 2, kc = blk & 3;
    int tid = threadIdx.x;
    size_t ubase = (size_t)blk * 18432;
#pragma unroll
    for (int i = 0; i < 4; i++) {
        int idx = tid + i * 256;
        int r = half * 64 + (idx >> 4), c4 = (idx & 15) * 4;
        float4 v = *(const float4*)&src[(size_t)(nh2 * 128 + r) * EE + kc * 64 + c4];
        uint2 s0 = splitpack(v.x, v.y);
        uint2 s1 = splitpack(v.z, v.w);
        ushortT* hp = dst + ubase + r * 72 + c4;
        *(unsigned*)hp = s0.x; *(unsigned*)(hp + 2) = s1.x;
        ushortT* lp = hp + 9216;
        *(unsigned*)lp = s0.y; *(unsigned*)(lp + 2) = s1.y;
    }
}

// ================= pipelined mma.sync split-bf16 GEMM (K/V projections) =================
#define EPI_FEAT  1
#define EPI_VPROJ 2
#define PITCHB 144
#define TILEB (128*PITCHB)    // 18432 B
#define BSTAGE (2*TILEB)
#define SMEM_SZ (2*TILEB + 2*BSTAGE)   // 110592 B

extern __shared__ char dyn_smem[];

__global__ void __launch_bounds__(512, 2) tgemm(
    const float* __restrict__ A0, const float* __restrict__ A1,
    const ushortT* __restrict__ Bsp, int bStrideZ,
    const float* __restrict__ bias0, const float* __restrict__ bias1,
    float* __restrict__ C0, float* __restrict__ C1,
    int epi0, int epi1,
    const void* __restrict__ mask, float scale)
{
    int z = blockIdx.z;
    const float* A    = z == 0 ? A0 : A1;
    const float* bias = z == 0 ? bias0 : bias1;
    float* C          = z == 0 ? C0 : C1;
    int epi           = z == 0 ? epi0 : epi1;

    uint32_t AhU = smem_u32(dyn_smem);
    uint32_t AlU = AhU + TILEB;
    uint32_t BsU = AhU + 2 * TILEB;

    int tid = threadIdx.x, wid = tid >> 5, lane = tid & 31;
    int wm = wid >> 2, wn = wid & 3;
    int bm = blockIdx.y * 128, bn = blockIdx.x * 128;
    const ushortT* B = Bsp + (size_t)z * bStrideZ;

    int lmat = lane >> 3, lrow = lane & 7;
    int a_roff = ((lmat & 1) ? 8 : 0) + lrow;
    int a_coff = (lmat & 2) ? 16 : 0;
    int b_roff = ((lmat & 2) ? 8 : 0) + lrow;
    int b_coff = (lmat & 1) ? 16 : 0;

    float acc[2][4][4];
#pragma unroll
    for (int mi = 0; mi < 2; mi++)
#pragma unroll
        for (int ni = 0; ni < 4; ni++)
#pragma unroll
            for (int j = 0; j < 4; j++) acc[mi][ni][j] = 0.f;

    float4 pf[4];

#define ISSUE_B(kc, stage) do { \
        const char* _src = (const char*)(B + (size_t)(blockIdx.x * 4 + (kc)) * 18432); \
        uint32_t _db = BsU + (stage) * BSTAGE; \
        _Pragma("unroll") \
        for (int _j = 0; _j < 5; _j++) { \
            int _id = tid + _j * 512; \
            if (_id < 2304) \
                asm volatile("cp.async.cg.shared.global [%0], [%1], 16;" \
                    :: "r"(_db + _id * 16), "l"(_src + _id * 16)); \
        } \
        asm volatile("cp.async.commit_group;" ::: "memory"); \
    } while (0)

#define LOAD_A(kc) do { \
        _Pragma("unroll") \
        for (int _i = 0; _i < 4; _i++) { \
            int _idx = tid + _i * 512; \
            int _r = _idx >> 4, _c4 = (_idx & 15) << 2; \
            pf[_i] = *(const float4*)&A[(size_t)(bm + _r) * EE + (kc) * 64 + _c4]; \
        } \
    } while (0)

#define STORE_A() do { \
        _Pragma("unroll") \
        for (int _i = 0; _i < 4; _i++) { \
            int _idx = tid + _i * 512; \
            int _r = _idx >> 4, _c4 = (_idx & 15) << 2; \
            uint32_t _off = _r * PITCHB + _c4 * 2; \
            uint2 _s0 = splitpack(pf[_i].x, pf[_i].y); \
            uint2 _s1 = splitpack(pf[_i].z, pf[_i].w); \
            asm volatile("st.shared.v2.b32 [%0], {%1,%2};" :: "r"(AhU + _off), "r"(_s0.x), "r"(_s1.x) : "memory"); \
            asm volatile("st.shared.v2.b32 [%0], {%1,%2};" :: "r"(AlU + _off), "r"(_s0.y), "r"(_s1.y) : "memory"); \
        } \
    } while (0)

    ISSUE_B(0, 0);
    LOAD_A(0);
    STORE_A();
    asm volatile("cp.async.wait_group 0;" ::: "memory");
    __syncthreads();

    for (int kc = 0; kc < 4; kc++) {
        int s = kc & 1;
        if (kc < 3) {
            ISSUE_B(kc + 1, s ^ 1);
            LOAD_A(kc + 1);
        }
        uint32_t BhU = BsU + s * BSTAGE;
        uint32_t BlU = BhU + TILEB;
#pragma unroll
        for (int ks = 0; ks < 4; ks++) {
            int cbb = ks * 32;
            unsigned ah[2][4], bh[4][2], bx[4][2], tmp[4];
#pragma unroll
            for (int mi = 0; mi < 2; mi++) {
                int rb = wm * 32 + mi * 16;
                ldsm4(ah[mi], AhU + (rb + a_roff) * PITCHB + cbb + a_coff);
            }
#pragma unroll
            for (int p = 0; p < 2; p++) {
                int nb = wn * 32 + p * 16;
                ldsm4(tmp, BhU + (nb + b_roff) * PITCHB + cbb + b_coff);
                bh[2*p][0] = tmp[0]; bh[2*p][1] = tmp[1];
                bh[2*p+1][0] = tmp[2]; bh[2*p+1][1] = tmp[3];
            }
#pragma unroll
            for (int mi = 0; mi < 2; mi++)
#pragma unroll
                for (int ni = 0; ni < 4; ni++) mma16816(acc[mi][ni], ah[mi], bh[ni]);
#pragma unroll
            for (int p = 0; p < 2; p++) {
                int nb = wn * 32 + p * 16;
                ldsm4(tmp, BlU + (nb + b_roff) * PITCHB + cbb + b_coff);
                bx[2*p][0] = tmp[0]; bx[2*p][1] = tmp[1];
                bx[2*p+1][0] = tmp[2]; bx[2*p+1][1] = tmp[3];
            }
#pragma unroll
            for (int mi = 0; mi < 2; mi++)
#pragma unroll
                for (int ni = 0; ni < 4; ni++) mma16816(acc[mi][ni], ah[mi], bx[ni]);
#pragma unroll
            for (int mi = 0; mi < 2; mi++) {
                int rb = wm * 32 + mi * 16;
                ldsm4(ah[mi], AlU + (rb + a_roff) * PITCHB + cbb + a_coff);
            }
#pragma unroll
            for (int mi = 0; mi < 2; mi++)
#pragma unroll
                for (int ni = 0; ni < 4; ni++) mma16816(acc[mi][ni], ah[mi], bh[ni]);
        }
        __syncthreads();
        if (kc < 3) {
            STORE_A();
            asm volatile("cp.async.wait_group 0;" ::: "memory");
            __syncthreads();
        }
    }

    // ---- epilogue: EPI_FEAT / EPI_VPROJ -> fp32 row-major ----
    int g = lane >> 2, tc = lane & 3;
#pragma unroll
    for (int mi = 0; mi < 2; mi++) {
        int r0 = bm + wm * 32 + mi * 16 + g;
        int r1 = r0 + 8;
        float mv0 = mask_val(mask, r0), mv1 = mask_val(mask, r1);
#pragma unroll
        for (int ni = 0; ni < 4; ni++) {
            int col = bn + wn * 32 + ni * 8 + tc * 2;
            float c0 = acc[mi][ni][0], c1 = acc[mi][ni][1];
            float c2 = acc[mi][ni][2], c3 = acc[mi][ni][3];
            float b0 = bias[col], b1 = bias[col + 1];
            if (epi == EPI_FEAT) {
                c0 += b0; c1 += b1; c2 += b0; c3 += b1;
                c0 = (c0 > 0.f ? c0 + 1.f : expf(c0)) * mv0;
                c1 = (c1 > 0.f ? c1 + 1.f : expf(c1)) * mv0;
                c2 = (c2 > 0.f ? c2 + 1.f : expf(c2)) * mv1;
                c3 = (c3 > 0.f ? c3 + 1.f : expf(c3)) * mv1;
            } else {
                c0 = (c0 + b0) * mv0 * scale; c1 = (c1 + b1) * mv0 * scale;
                c2 = (c2 + b0) * mv1 * scale; c3 = (c3 + b1) * mv1 * scale;
            }
            *(float2*)&C[(size_t)r0 * EE + col] = make_float2(c0, c1);
            *(float2*)&C[(size_t)r1 * EE + col] = make_float2(c2, c3);
        }
    }
#undef ISSUE_B
#undef LOAD_A
#undef STORE_A
}

// ================= fused Q-projection + Z-fold + final GEMM =================
// smem: [0,147456) Qsp (4 kc x (hi 18432 | lo 18432));
//       [147456,184320) conv A hi|lo (phase1) / B stage 0 (phase2);
//       [184320,221184) B buffer (phase1 single) / B stage 1 (phase2)
#define QSP_BYTES 147456
#define CONV_OFF 147456
#define BBUF_OFF 184320
#define SMEM_QO 221184

__global__ void __launch_bounds__(512) qout(
    const float* __restrict__ A, const float* __restrict__ bias,
    float* __restrict__ Cout, const void* __restrict__ mask)
{
    uint32_t QsU = smem_u32(dyn_smem);
    uint32_t AhU = QsU + CONV_OFF;
    uint32_t AlU = AhU + TILEB;
    uint32_t BbU = QsU + BBUF_OFF;

    int tid = threadIdx.x, wid = tid >> 5, lane = tid & 31;
    int wm = wid >> 2, wn = wid & 3;
    int bm = blockIdx.x * 128;
    int n = bm >> 12;

    int lmat = lane >> 3, lrow = lane & 7;
    int a_roff = ((lmat & 1) ? 8 : 0) + lrow;
    int a_coff = (lmat & 2) ? 16 : 0;
    int b_roff = ((lmat & 2) ? 8 : 0) + lrow;
    int b_coff = (lmat & 1) ? 16 : 0;
    int g = lane >> 2, tc = lane & 3;

    float4 pf[4];

    // ---------- Phase 1: Qf*Z -> Qsp (smem), two 128-col passes ----------
    for (int bn2 = 0; bn2 < 2; bn2++) {
        int bn = bn2 * 128;
        float acc[2][4][4];
#pragma unroll
        for (int mi = 0; mi < 2; mi++)
#pragma unroll
            for (int ni = 0; ni < 4; ni++)
#pragma unroll
                for (int j = 0; j < 4; j++) acc[mi][ni][j] = 0.f;

        for (int kc = 0; kc < 4; kc++) {
            // issue Wq tile (single-buffered; Wq is L2-hot)
            {
                const char* src = (const char*)(g_Wsp + (size_t)(bn2 * 4 + kc) * 18432);
#pragma unroll
                for (int j = 0; j < 5; j++) {
                    int id = tid + j * 512;
                    if (id < 2304)
                        asm volatile("cp.async.cg.shared.global [%0], [%1], 16;"
                            :: "r"(BbU + id * 16), "l"(src + id * 16));
                }
                asm volatile("cp.async.commit_group;" ::: "memory");
            }
            // load q fp32 + split into conv buffers
#pragma unroll
            for (int i = 0; i < 4; i++) {
                int idx = tid + i * 512;
                int r = idx >> 4, c4 = (idx & 15) << 2;
                pf[i] = *(const float4*)&A[(size_t)(bm + r) * EE + kc * 64 + c4];
            }
#pragma unroll
            for (int i = 0; i < 4; i++) {
                int idx = tid + i * 512;
                int r = idx >> 4, c4 = (idx & 15) << 2;
                uint32_t off = r * PITCHB + c4 * 2;
                uint2 s0 = splitpack(pf[i].x, pf[i].y);
                uint2 s1 = splitpack(pf[i].z, pf[i].w);
                asm volatile("st.shared.v2.b32 [%0], {%1,%2};" :: "r"(AhU + off), "r"(s0.x), "r"(s1.x) : "memory");
                asm volatile("st.shared.v2.b32 [%0], {%1,%2};" :: "r"(AlU + off), "r"(s0.y), "r"(s1.y) : "memory");
            }
            asm volatile("cp.async.wait_group 0;" ::: "memory");
            __syncthreads();
            uint32_t BhU = BbU, BlU = BbU + TILEB;
#pragma unroll
            for (int ks = 0; ks < 4; ks++) {
                int cbb = ks * 32;
                unsigned ah[2][4], bh[4][2], bx[4][2], tmp[4];
#pragma unroll
                for (int mi = 0; mi < 2; mi++) {
                    int rb = wm * 32 + mi * 16;
                    ldsm4(ah[mi], AhU + (rb + a_roff) * PITCHB + cbb + a_coff);
                }
#pragma unroll
                for (int p = 0; p < 2; p++) {
                    int nb = wn * 32 + p * 16;
                    ldsm4(tmp, BhU + (nb + b_roff) * PITCHB + cbb + b_coff);
                    bh[2*p][0] = tmp[0]; bh[2*p][1] = tmp[1];
                    bh[2*p+1][0] = tmp[2]; bh[2*p+1][1] = tmp[3];
                }
#pragma unroll
                for (int mi = 0; mi < 2; mi++)
#pragma unroll
                    for (int ni = 0; ni < 4; ni++) mma16816(acc[mi][ni], ah[mi], bh[ni]);
#pragma unroll
                for (int p = 0; p < 2; p++) {
                    int nb = wn * 32 + p * 16;
                    ldsm4(tmp, BlU + (nb + b_roff) * PITCHB + cbb + b_coff);
                    bx[2*p][0] = tmp[0]; bx[2*p][1] = tmp[1];
                    bx[2*p+1][0] = tmp[2]; bx[2*p+1][1] = tmp[3];
                }
#pragma unroll
                for (int mi = 0; mi < 2; mi++)
#pragma unroll
                    for (int ni = 0; ni < 4; ni++) mma16816(acc[mi][ni], ah[mi], bx[ni]);
#pragma unroll
                for (int mi = 0; mi < 2; mi++) {
                    int rb = wm * 32 + mi * 16;
                    ldsm4(ah[mi], AlU + (rb + a_roff) * PITCHB + cbb + a_coff);
                }
#pragma unroll
                for (int mi = 0; mi < 2; mi++)
#pragma unroll
                    for (int ni = 0; ni < 4; ni++) mma16816(acc[mi][ni], ah[mi], bh[ni]);
            }
            __syncthreads();
        }

        // epilogue: feature map + mask + Z fold, write split-bf16 into Qsp smem
        int h = (bn + wn * 32) >> 5;
        const float* ksp = g_KV + (size_t)(n * HH + h) * 1056 + 1024;
#pragma unroll
        for (int mi = 0; mi < 2; mi++) {
            int r0 = bm + wm * 32 + mi * 16 + g;
            int r1 = r0 + 8;
            float mv0 = mask_val(mask, r0), mv1 = mask_val(mask, r1);
            float cb[4][4];
            float p0 = 0.f, p1 = 0.f;
#pragma unroll
            for (int ni = 0; ni < 4; ni++) {
                int col = bn + wn * 32 + ni * 8 + tc * 2;
                int d = ni * 8 + tc * 2;
                float b0 = bias[col], b1 = bias[col + 1];
                float c0 = acc[mi][ni][0] + b0, c1 = acc[mi][ni][1] + b1;
                float c2 = acc[mi][ni][2] + b0, c3 = acc[mi][ni][3] + b1;
                c0 = (c0 > 0.f ? c0 + 1.f : expf(c0)) * mv0;
                c1 = (c1 > 0.f ? c1 + 1.f : expf(c1)) * mv0;
                c2 = (c2 > 0.f ? c2 + 1.f : expf(c2)) * mv1;
                c3 = (c3 > 0.f ? c3 + 1.f : expf(c3)) * mv1;
                float k0 = ksp[d], k1 = ksp[d + 1];
                p0 += c0 * k0 + c1 * k1;
                p1 += c2 * k0 + c3 * k1;
                cb[ni][0] = c0; cb[ni][1] = c1; cb[ni][2] = c2; cb[ni][3] = c3;
            }
            p0 += __shfl_xor_sync(0xffffffffu, p0, 1);
            p0 += __shfl_xor_sync(0xffffffffu, p0, 2);
            p1 += __shfl_xor_sync(0xffffffffu, p1, 1);
            p1 += __shfl_xor_sync(0xffffffffu, p1, 2);
            float z0 = 1.f / (p0 + EPSV), z1 = 1.f / (p1 + EPSV);
            int lr0 = wm * 32 + mi * 16 + g, lr1 = lr0 + 8;
#pragma unroll
            for (int ni = 0; ni < 4; ni++) {
                int col = bn + wn * 32 + ni * 8 + tc * 2;
                int kcb = col >> 6, cc = col & 63;
                uint2 s0 = splitpack(cb[ni][0] * z0, cb[ni][1] * z0);
                uint2 s1 = splitpack(cb[ni][2] * z1, cb[ni][3] * z1);
                uint32_t base = QsU + kcb * 36864 + cc * 2;
                asm volatile("st.shared.b32 [%0], %1;" :: "r"(base + lr0 * PITCHB), "r"(s0.x) : "memory");
                asm volatile("st.shared.b32 [%0], %1;" :: "r"(base + lr0 * PITCHB + TILEB), "r"(s0.y) : "memory");
                asm volatile("st.shared.b32 [%0], %1;" :: "r"(base + lr1 * PITCHB), "r"(s1.x) : "memory");
                asm volatile("st.shared.b32 [%0], %1;" :: "r"(base + lr1 * PITCHB + TILEB), "r"(s1.y) : "memory");
            }
        }
    }

    // ---------- Phase 2: (Qf*Z) @ UT^T, A resident in smem ----------
    const ushortT* UT = g_UTsp + (size_t)n * MATU;
    for (int bn2 = 0; bn2 < 2; bn2++) {
        float acc[2][4][4];
#pragma unroll
        for (int mi = 0; mi < 2; mi++)
#pragma unroll
            for (int ni = 0; ni < 4; ni++)
#pragma unroll
                for (int j = 0; j < 4; j++) acc[mi][ni][j] = 0.f;

#define ISSUE_UT(kc, st) do { \
        const char* _src = (const char*)(UT + (size_t)(bn2 * 4 + (kc)) * 18432); \
        uint32_t _db = (st) ? BbU : (QsU + CONV_OFF); \
        _Pragma("unroll") \
        for (int _j = 0; _j < 5; _j++) { \
            int _id = tid + _j * 512; \
            if (_id < 2304) \
                asm volatile("cp.async.cg.shared.global [%0], [%1], 16;" \
                    :: "r"(_db + _id * 16), "l"(_src + _id * 16)); \
        } \
        asm volatile("cp.async.commit_group;" ::: "memory"); \
    } while (0)

        ISSUE_UT(0, 0);
        ISSUE_UT(1, 1);

        for (int kc = 0; kc < 4; kc++) {
            int st = kc & 1;
            if (kc == 3) asm volatile("cp.async.wait_group 0;" ::: "memory");
            else         asm volatile("cp.async.wait_group 1;" ::: "memory");
            __syncthreads();
            uint32_t Ah2 = QsU + kc * 36864, Al2 = Ah2 + TILEB;
            uint32_t Bh2 = st ? BbU : (QsU + CONV_OFF), Bl2 = Bh2 + TILEB;
#pragma unroll
            for (int ks = 0; ks < 4; ks++) {
                int cbb = ks * 32;
                unsigned ah[2][4], bh[4][2], bx[4][2], tmp[4];
#pragma unroll
                for (int mi = 0; mi < 2; mi++) {
                    int rb = wm * 32 + mi * 16;
                    ldsm4(ah[mi], Ah2 + (rb + a_roff) * PITCHB + cbb + a_coff);
                }
#pragma unroll
                for (int p = 0; p < 2; p++) {
                    int nb = wn * 32 + p * 16;
                    ldsm4(tmp, Bh2 + (nb + b_roff) * PITCHB + cbb + b_coff);
                    bh[2*p][0] = tmp[0]; bh[2*p][1] = tmp[1];
                    bh[2*p+1][0] = tmp[2]; bh[2*p+1][1] = tmp[3];
                }
#pragma unroll
                for (int mi = 0; mi < 2; mi++)
#pragma unroll
                    for (int ni = 0; ni < 4; ni++) mma16816(acc[mi][ni], ah[mi], bh[ni]);
#pragma unroll
                for (int p = 0; p < 2; p++) {
                    int nb = wn * 32 + p * 16;
                    ldsm4(tmp, Bl2 + (nb + b_roff) * PITCHB + cbb + b_coff);
                    bx[2*p][0] = tmp[0]; bx[2*p][1] = tmp[1];
                    bx[2*p+1][0] = tmp[2]; bx[2*p+1][1] = tmp[3];
                }
#pragma unroll
                for (int mi = 0; mi < 2; mi++)
#pragma unroll
                    for (int ni = 0; ni < 4; ni++) mma16816(acc[mi][ni], ah[mi], bx[ni]);
#pragma unroll
                for (int mi = 0; mi < 2; mi++) {
                    int rb = wm * 32 + mi * 16;
                    ldsm4(ah[mi], Al2 + (rb + a_roff) * PITCHB + cbb + a_coff);
                }
#pragma unroll
                for (int mi = 0; mi < 2; mi++)
#pragma unroll
                    for (int ni = 0; ni < 4; ni++) mma16816(acc[mi][ni], ah[mi], bh[ni]);
            }
            __syncthreads();
            if (kc < 2) ISSUE_UT(kc + 2, st);
        }
#undef ISSUE_UT

#pragma unroll
        for (int mi = 0; mi < 2; mi++) {
            int r0 = bm + wm * 32 + mi * 16 + g;
            int r1 = r0 + 8;
#pragma unroll
            for (int ni = 0; ni < 4; ni++) {
                int col = bn2 * 128 + wn * 32 + ni * 8 + tc * 2;
                *(float2*)&Cout[(size_t)r0 * EE + col] = make_float2(acc[mi][ni][0], acc[mi][ni][1]);
                *(float2*)&Cout[(size_t)r1 * EE + col] = make_float2(acc[mi][ni][2], acc[mi][ni][3]);
            }
        }
    }
}

// ---------------- KV aggregation: register-tiled partial sums ----------------
__global__ __launch_bounds__(256) void kv_partial() {
    int nh = blockIdx.x;
    int n = nh >> 3, h = nh & 7;
    int chunk = blockIdx.y;
    __shared__ float Ks[64][32];
    __shared__ float Vs[64][32];
    __shared__ float red[4][1056];
    int tid = threadIdx.x;
    int grp = tid >> 6;
    int gt = tid & 63;
    int dg = gt >> 3;
    int vg = gt & 7;
    float acc[4][4] = {};
    float ks[4] = {};
    int s0base = chunk * CHS;
    const float* Kp = g_Kf + (size_t)n * SS * EE + h * DD;
    const float* Vp = g_Vm + (size_t)n * SS * EE + h * DD;
    for (int s0 = 0; s0 < CHS; s0 += 64) {
#pragma unroll
        for (int r = 0; r < 2; r++) {
            int idx = tid + r * 256;
            int row = idx >> 3, c = (idx & 7) * 4;
            size_t gidx = (size_t)(s0base + s0 + row) * EE + c;
            *(float4*)&Ks[row][c] = *(const float4*)&Kp[gidx];
            *(float4*)&Vs[row][c] = *(const float4*)&Vp[gidx];
        }
        __syncthreads();
#pragma unroll
        for (int si = 0; si < 16; si++) {
            int s = grp * 16 + si;
            float4 kk = *(const float4*)&Ks[s][dg * 4];
            float4 vv = *(const float4*)&Vs[s][vg * 4];
            float ka[4] = {kk.x, kk.y, kk.z, kk.w};
            float va[4] = {vv.x, vv.y, vv.z, vv.w};
#pragma unroll
            for (int i = 0; i < 4; i++) {
                ks[i] += ka[i];
#pragma unroll
                for (int j = 0; j < 4; j++) acc[i][j] += ka[i] * va[j];
            }
        }
        __syncthreads();
    }
#pragma unroll
    for (int i = 0; i < 4; i++)
#pragma unroll
        for (int j = 0; j < 4; j++)
            red[grp][(dg * 4 + i) * 32 + vg * 4 + j] = acc[i][j];
    if (vg == 0) {
#pragma unroll
        for (int i = 0; i < 4; i++) red[grp][1024 + dg * 4 + i] = ks[i];
    }
    __syncthreads();
    float* P = g_part + ((size_t)chunk * 64 + nh) * 1056;
    for (int i = tid; i < 1056; i += 256)
        P[i] = red[0][i] + red[1][i] + red[2][i] + red[3][i];
}

// ---------------- fused: reduce partials + write Ksum + emit split-bf16 UT ----------------
__global__ __launch_bounds__(256) void finalize_kv(const float* __restrict__ Wm) {
    int nh = blockIdx.x; int n = nh >> 3, h = nh & 7;
    __shared__ float KVs[32][32];
    int tid = threadIdx.x;
    for (int i = tid; i < 1056; i += 256) {
        float s = 0;
#pragma unroll
        for (int c = 0; c < NCHUNK; c++) s += g_part[((size_t)c * 64 + nh) * 1056 + i];
        if (i < 1024) KVs[i >> 5][i & 31] = s;
        else g_KV[(size_t)nh * 1056 + i] = s;
    }
    __syncthreads();
    int ep = tid;
    float w[32];
#pragma unroll
    for (int v = 0; v < 32; v++) w[v] = Wm[(size_t)ep * EE + h * DD + v];
    ushortT* dsth = g_UTsp + (size_t)n * MATU
                  + ((size_t)((ep >> 7) * 4 + (h >> 1))) * 18432
                  + (ep & 127) * 72 + (h & 1) * 32;
#pragma unroll
    for (int d2 = 0; d2 < 32; d2++) {
        float a = 0;
#pragma unroll
        for (int v = 0; v < 32; v++) a += KVs[d2][v] * w[v];
        a *= (float)SS;
        __nv_bfloat16 hb = __float2bfloat16(a);
        float hr = __bfloat162float(hb);
        __nv_bfloat16 lb = __float2bfloat16(a - hr);
        dsth[d2] = __bfloat16_as_ushort(hb);
        dsth[9216 + d2] = __bfloat16_as_ushort(lb);
    }
}

// ---------------- launch ----------------
extern "C" void kernel_launch(void* const* d_in, const int* in_sizes, int n_in,
                              void* d_out, int out_size) {
    const float* q  = (const float*)d_in[0];
    const float* k  = (const float*)d_in[1];
    const float* v  = (const float*)d_in[2];
    const void*  qm = d_in[3];
    const void*  km = d_in[4];
    const float* Wq = (const float*)d_in[5];
    const float* bq = (const float*)d_in[6];
    const float* Wk = (const float*)d_in[7];
    const float* bk = (const float*)d_in[8];
    const float* Wv = (const float*)d_in[9];
    const float* bv = (const float*)d_in[10];
    const float* Wm = (const float*)d_in[11];
    float* out = (float*)d_out;

    float *Kf, *Vm;
    ushortT *Wsp;
    cudaGetSymbolAddress((void**)&Kf, g_Kf);
    cudaGetSymbolAddress((void**)&Vm, g_Vm);
    cudaGetSymbolAddress((void**)&Wsp, g_Wsp);

    cudaFuncSetAttribute(tgemm, cudaFuncAttributeMaxDynamicSharedMemorySize, SMEM_SZ);
    cudaFuncSetAttribute(qout, cudaFuncAttributeMaxDynamicSharedMemorySize, SMEM_QO);

    detect_mask_kernel<<<1, 256>>>((const unsigned int*)km, 2048);
    split_w3<<<dim3(16, 3), 256>>>(Wq, Wk, Wv);

    // K and V projections (fused, z = 2)
    tgemm<<<dim3(2, NTOK / 128, 2), 512, SMEM_SZ>>>(
        k, v, Wsp + MATU, MATU,
        bk, bv, Kf, Vm,
        EPI_FEAT, EPI_VPROJ,
        km, 1.f / (float)SS);

    kv_partial<<<dim3(64, NCHUNK), 256>>>();
    finalize_kv<<<64, 256>>>(Wm);

    // fused Q-projection (with Z fold) + final merge GEMM
    qout<<<NTOK / 128, 512, SMEM_QO>>>(q, bq, out, qm);
}

// round 15
// speedup vs baseline: 1.4936x; 1.0089x over previous
#include <cuda_runtime.h>
#include <cuda_bf16.h>
#include <cstdint>

#define Nb 8
#define LL 4096
#define SS 4096
#define EE 256
#define HH 8
#define DD 32
#define NTOK (Nb*LL)
#define EPSV 1e-6f
#define NCHUNK 8
#define CHS (SS/NCHUNK)

typedef unsigned short ushortT;

// ---------------- scratch ----------------
__device__ float g_Kf[Nb*SS*EE];
__device__ float g_Vm[Nb*SS*EE];
__device__ float g_part[NCHUNK*Nb*HH*1056];
__device__ float g_KV[Nb*HH*1056];     // Ksum at [1024..1055]
__device__ int   g_mask_kind;
#define MATU 147456                    // ushorts per 256x256 split matrix
__device__ ushortT g_Wsp[3*MATU];      // Wq, Wk, Wv  (tiled hi/lo bf16)
__device__ ushortT g_UTsp[Nb*MATU];    // per-batch UT (tiled hi/lo bf16)

// ---------------- helpers ----------------
__device__ __forceinline__ uint32_t smem_u32(const void* p) {
    uint32_t a;
    asm("{ .reg .u64 t; cvta.to.shared.u64 t, %1; cvt.u32.u64 %0, t; }" : "=r"(a) : "l"(p));
    return a;
}
__device__ __forceinline__ void ldsm4(unsigned* r, uint32_t addr) {
    asm volatile("ldmatrix.sync.aligned.m8n8.x4.shared.b16 {%0,%1,%2,%3}, [%4];"
        : "=r"(r[0]), "=r"(r[1]), "=r"(r[2]), "=r"(r[3]) : "r"(addr));
}
__device__ __forceinline__ void mma16816(float* c, const unsigned* a, const unsigned* b) {
    asm volatile("mma.sync.aligned.m16n8k16.row.col.f32.bf16.bf16.f32 "
        "{%0,%1,%2,%3}, {%4,%5,%6,%7}, {%8,%9}, {%0,%1,%2,%3};"
        : "+f"(c[0]), "+f"(c[1]), "+f"(c[2]), "+f"(c[3])
        : "r"(a[0]), "r"(a[1]), "r"(a[2]), "r"(a[3]), "r"(b[0]), "r"(b[1]));
}
__device__ __forceinline__ uint2 splitpack(float x0, float x1) {
    __nv_bfloat162 h = __float22bfloat162_rn(make_float2(x0, x1));
    float2 hf = __bfloat1622float2(h);
    __nv_bfloat162 l = __float22bfloat162_rn(make_float2(x0 - hf.x, x1 - hf.y));
    uint2 o;
    o.x = *(unsigned*)&h;
    o.y = *(unsigned*)&l;
    return o;
}

// ---------------- mask dtype detection ----------------
__global__ void detect_mask_kernel(const unsigned int* __restrict__ m, int nwords) {
    __shared__ int flags[3];
    if (threadIdx.x < 3) flags[threadIdx.x] = 0;
    __syncthreads();
    for (int i = threadIdx.x; i < nwords; i += blockDim.x) {
        unsigned w = m[i];
        if (w == 0x3F803F80u || w == 0x00003F80u) atomicOr(&flags[0], 1);
        else if (w == 0x3F800000u) atomicOr(&flags[1], 1);
        else if (w > 1u) {
            unsigned b0 = w & 255u, b1 = (w >> 8) & 255u, b2 = (w >> 16) & 255u, b3 = w >> 24;
            if (b0 <= 1u && b1 <= 1u && b2 <= 1u && b3 <= 1u) atomicOr(&flags[2], 1);
        }
    }
    __syncthreads();
    if (threadIdx.x == 0) {
        int kind;
        if (flags[0]) kind = 3;
        else if (flags[1]) kind = 2;
        else if (flags[2]) kind = 0;
        else kind = 1;
        g_mask_kind = kind;
    }
}

__device__ __forceinline__ float mask_val(const void* p, int i) {
    int k = g_mask_kind;
    if (k == 0) return ((const unsigned char*)p)[i] ? 1.f : 0.f;
    if (k == 1) return ((const int*)p)[i] ? 1.f : 0.f;
    if (k == 2) return ((const float*)p)[i];
    return __bfloat162float(((const __nv_bfloat16*)p)[i]);
}

// ---------------- pre-split the 3 weight matrices ----------------
__global__ __launch_bounds__(256) void split_w3(const float* __restrict__ W0,
                                                const float* __restrict__ W1,
                                                const float* __restrict__ W2) {
    int y = blockIdx.y;
    const float* src = y == 0 ? W0 : (y == 1 ? W1 : W2);
    ushortT* dst = g_Wsp + (size_t)y * MATU;
    int blk = blockIdx.x >> 1;
    int half = blockIdx.x & 1;
    int nh2 = blk >> 2, kc = blk & 3;
    int tid = threadIdx.x;
    size_t ubase = (size_t)blk * 18432;
#pragma unroll
    for (int i = 0; i < 4; i++) {
        int idx = tid + i * 256;
        int r = half * 64 + (idx >> 4), c4 = (idx & 15) * 4;
        float4 v = *(const float4*)&src[(size_t)(nh2 * 128 + r) * EE + kc * 64 + c4];
        uint2 s0 = splitpack(v.x, v.y);
        uint2 s1 = splitpack(v.z, v.w);
        ushortT* hp = dst + ubase + r * 72 + c4;
        *(unsigned*)hp = s0.x; *(unsigned*)(hp + 2) = s1.x;
        ushortT* lp = hp + 9216;
        *(unsigned*)lp = s0.y; *(unsigned*)(lp + 2) = s1.y;
    }
}

// ================= pipelined mma.sync split-bf16 GEMM (K/V projections) =================
#define EPI_FEAT  1
#define EPI_VPROJ 2
#define PITCHB 144
#define TILEB (128*PITCHB)    // 18432 B
#define BSTAGE (2*TILEB)
#define SMEM_SZ (2*TILEB + 2*BSTAGE)   // 110592 B

extern __shared__ char dyn_smem[];

__global__ void __launch_bounds__(512, 2) tgemm(
    const float* __restrict__ A0, const float* __restrict__ A1,
    const ushortT* __restrict__ Bsp, int bStrideZ,
    const float* __restrict__ bias0, const float* __restrict__ bias1,
    float* __restrict__ C0, float* __restrict__ C1,
    int epi0, int epi1,
    const void* __restrict__ mask, float scale)
{
    int z = blockIdx.z;
    const float* A    = z == 0 ? A0 : A1;
    const float* bias = z == 0 ? bias0 : bias1;
    float* C          = z == 0 ? C0 : C1;
    int epi           = z == 0 ? epi0 : epi1;

    uint32_t AhU = smem_u32(dyn_smem);
    uint32_t AlU = AhU + TILEB;
    uint32_t BsU = AhU + 2 * TILEB;

    int tid = threadIdx.x, wid = tid >> 5, lane = tid & 31;
    int wm = wid >> 2, wn = wid & 3;
    int bm = blockIdx.y * 128, bn = blockIdx.x * 128;
    const ushortT* B = Bsp + (size_t)z * bStrideZ;

    int lmat = lane >> 3, lrow = lane & 7;
    int a_roff = ((lmat & 1) ? 8 : 0) + lrow;
    int a_coff = (lmat & 2) ? 16 : 0;
    int b_roff = ((lmat & 2) ? 8 : 0) + lrow;
    int b_coff = (lmat & 1) ? 16 : 0;

    float acc[2][4][4];
#pragma unroll
    for (int mi = 0; mi < 2; mi++)
#pragma unroll
        for (int ni = 0; ni < 4; ni++)
#pragma unroll
            for (int j = 0; j < 4; j++) acc[mi][ni][j] = 0.f;

    float4 pf[4];

#define ISSUE_B(kc, stage) do { \
        const char* _src = (const char*)(B + (size_t)(blockIdx.x * 4 + (kc)) * 18432); \
        uint32_t _db = BsU + (stage) * BSTAGE; \
        _Pragma("unroll") \
        for (int _j = 0; _j < 5; _j++) { \
            int _id = tid + _j * 512; \
            if (_id < 2304) \
                asm volatile("cp.async.cg.shared.global [%0], [%1], 16;" \
                    :: "r"(_db + _id * 16), "l"(_src + _id * 16)); \
        } \
        asm volatile("cp.async.commit_group;" ::: "memory"); \
    } while (0)

#define LOAD_A(kc) do { \
        _Pragma("unroll") \
        for (int _i = 0; _i < 4; _i++) { \
            int _idx = tid + _i * 512; \
            int _r = _idx >> 4, _c4 = (_idx & 15) << 2; \
            pf[_i] = *(const float4*)&A[(size_t)(bm + _r) * EE + (kc) * 64 + _c4]; \
        } \
    } while (0)

#define STORE_A() do { \
        _Pragma("unroll") \
        for (int _i = 0; _i < 4; _i++) { \
            int _idx = tid + _i * 512; \
            int _r = _idx >> 4, _c4 = (_idx & 15) << 2; \
            uint32_t _off = _r * PITCHB + _c4 * 2; \
            uint2 _s0 = splitpack(pf[_i].x, pf[_i].y); \
            uint2 _s1 = splitpack(pf[_i].z, pf[_i].w); \
            asm volatile("st.shared.v2.b32 [%0], {%1,%2};" :: "r"(AhU + _off), "r"(_s0.x), "r"(_s1.x) : "memory"); \
            asm volatile("st.shared.v2.b32 [%0], {%1,%2};" :: "r"(AlU + _off), "r"(_s0.y), "r"(_s1.y) : "memory"); \
        } \
    } while (0)

    ISSUE_B(0, 0);
    LOAD_A(0);
    STORE_A();
    asm volatile("cp.async.wait_group 0;" ::: "memory");
    __syncthreads();

    for (int kc = 0; kc < 4; kc++) {
        int s = kc & 1;
        if (kc < 3) {
            ISSUE_B(kc + 1, s ^ 1);
            LOAD_A(kc + 1);
        }
        uint32_t BhU = BsU + s * BSTAGE;
        uint32_t BlU = BhU + TILEB;
#pragma unroll
        for (int ks = 0; ks < 4; ks++) {
            int cbb = ks * 32;
            unsigned ah[2][4], bh[4][2], bx[4][2], tmp[4];
#pragma unroll
            for (int mi = 0; mi < 2; mi++) {
                int rb = wm * 32 + mi * 16;
                ldsm4(ah[mi], AhU + (rb + a_roff) * PITCHB + cbb + a_coff);
            }
#pragma unroll
            for (int p = 0; p < 2; p++) {
                int nb = wn * 32 + p * 16;
                ldsm4(tmp, BhU + (nb + b_roff) * PITCHB + cbb + b_coff);
                bh[2*p][0] = tmp[0]; bh[2*p][1] = tmp[1];
                bh[2*p+1][0] = tmp[2]; bh[2*p+1][1] = tmp[3];
            }
#pragma unroll
            for (int mi = 0; mi < 2; mi++)
#pragma unroll
                for (int ni = 0; ni < 4; ni++) mma16816(acc[mi][ni], ah[mi], bh[ni]);
#pragma unroll
            for (int p = 0; p < 2; p++) {
                int nb = wn * 32 + p * 16;
                ldsm4(tmp, BlU + (nb + b_roff) * PITCHB + cbb + b_coff);
                bx[2*p][0] = tmp[0]; bx[2*p][1] = tmp[1];
                bx[2*p+1][0] = tmp[2]; bx[2*p+1][1] = tmp[3];
            }
#pragma unroll
            for (int mi = 0; mi < 2; mi++)
#pragma unroll
                for (int ni = 0; ni < 4; ni++) mma16816(acc[mi][ni], ah[mi], bx[ni]);
#pragma unroll
            for (int mi = 0; mi < 2; mi++) {
                int rb = wm * 32 + mi * 16;
                ldsm4(ah[mi], AlU + (rb + a_roff) * PITCHB + cbb + a_coff);
            }
#pragma unroll
            for (int mi = 0; mi < 2; mi++)
#pragma unroll
                for (int ni = 0; ni < 4; ni++) mma16816(acc[mi][ni], ah[mi], bh[ni]);
        }
        __syncthreads();
        if (kc < 3) {
            STORE_A();
            asm volatile("cp.async.wait_group 0;" ::: "memory");
            __syncthreads();
        }
    }

    // ---- epilogue: EPI_FEAT / EPI_VPROJ -> fp32 row-major ----
    int g = lane >> 2, tc = lane & 3;
#pragma unroll
    for (int mi = 0; mi < 2; mi++) {
        int r0 = bm + wm * 32 + mi * 16 + g;
        int r1 = r0 + 8;
        float mv0 = mask_val(mask, r0), mv1 = mask_val(mask, r1);
#pragma unroll
        for (int ni = 0; ni < 4; ni++) {
            int col = bn + wn * 32 + ni * 8 + tc * 2;
            float c0 = acc[mi][ni][0], c1 = acc[mi][ni][1];
            float c2 = acc[mi][ni][2], c3 = acc[mi][ni][3];
            float b0 = bias[col], b1 = bias[col + 1];
            if (epi == EPI_FEAT) {
                c0 += b0; c1 += b1; c2 += b0; c3 += b1;
                c0 = (c0 > 0.f ? c0 + 1.f : expf(c0)) * mv0;
                c1 = (c1 > 0.f ? c1 + 1.f : expf(c1)) * mv0;
                c2 = (c2 > 0.f ? c2 + 1.f : expf(c2)) * mv1;
                c3 = (c3 > 0.f ? c3 + 1.f : expf(c3)) * mv1;
            } else {
                c0 = (c0 + b0) * mv0 * scale; c1 = (c1 + b1) * mv0 * scale;
                c2 = (c2 + b0) * mv1 * scale; c3 = (c3 + b1) * mv1 * scale;
            }
            *(float2*)&C[(size_t)r0 * EE + col] = make_float2(c0, c1);
            *(float2*)&C[(size_t)r1 * EE + col] = make_float2(c2, c3);
        }
    }
#undef ISSUE_B
#undef LOAD_A
#undef STORE_A
}

// ================= fused Q-projection + Z-fold + final GEMM =================
#define QSP_BYTES 147456
#define CONV_OFF 147456
#define BBUF_OFF 184320
#define SMEM_QO 221184

__global__ void __launch_bounds__(512) qout(
    const float* __restrict__ A, const float* __restrict__ bias,
    float* __restrict__ Cout, const void* __restrict__ mask)
{
    uint32_t QsU = smem_u32(dyn_smem);
    uint32_t AhU = QsU + CONV_OFF;
    uint32_t AlU = AhU + TILEB;
    uint32_t BbU = QsU + BBUF_OFF;

    int tid = threadIdx.x, wid = tid >> 5, lane = tid & 31;
    int wm = wid >> 2, wn = wid & 3;
    int bm = blockIdx.x * 128;
    int n = bm >> 12;

    int lmat = lane >> 3, lrow = lane & 7;
    int a_roff = ((lmat & 1) ? 8 : 0) + lrow;
    int a_coff = (lmat & 2) ? 16 : 0;
    int b_roff = ((lmat & 2) ? 8 : 0) + lrow;
    int b_coff = (lmat & 1) ? 16 : 0;
    int g = lane >> 2, tc = lane & 3;

    float4 pf[4];

    // ---------- Phase 1: Qf*Z -> Qsp (smem), two 128-col passes ----------
    for (int bn2 = 0; bn2 < 2; bn2++) {
        int bn = bn2 * 128;
        float acc[2][4][4];
#pragma unroll
        for (int mi = 0; mi < 2; mi++)
#pragma unroll
            for (int ni = 0; ni < 4; ni++)
#pragma unroll
                for (int j = 0; j < 4; j++) acc[mi][ni][j] = 0.f;

        for (int kc = 0; kc < 4; kc++) {
            {
                const char* src = (const char*)(g_Wsp + (size_t)(bn2 * 4 + kc) * 18432);
#pragma unroll
                for (int j = 0; j < 5; j++) {
                    int id = tid + j * 512;
                    if (id < 2304)
                        asm volatile("cp.async.cg.shared.global [%0], [%1], 16;"
                            :: "r"(BbU + id * 16), "l"(src + id * 16));
                }
                asm volatile("cp.async.commit_group;" ::: "memory");
            }
#pragma unroll
            for (int i = 0; i < 4; i++) {
                int idx = tid + i * 512;
                int r = idx >> 4, c4 = (idx & 15) << 2;
                pf[i] = *(const float4*)&A[(size_t)(bm + r) * EE + kc * 64 + c4];
            }
#pragma unroll
            for (int i = 0; i < 4; i++) {
                int idx = tid + i * 512;
                int r = idx >> 4, c4 = (idx & 15) << 2;
                uint32_t off = r * PITCHB + c4 * 2;
                uint2 s0 = splitpack(pf[i].x, pf[i].y);
                uint2 s1 = splitpack(pf[i].z, pf[i].w);
                asm volatile("st.shared.v2.b32 [%0], {%1,%2};" :: "r"(AhU + off), "r"(s0.x), "r"(s1.x) : "memory");
                asm volatile("st.shared.v2.b32 [%0], {%1,%2};" :: "r"(AlU + off), "r"(s0.y), "r"(s1.y) : "memory");
            }
            asm volatile("cp.async.wait_group 0;" ::: "memory");
            __syncthreads();
            uint32_t BhU = BbU, BlU = BbU + TILEB;
#pragma unroll
            for (int ks = 0; ks < 4; ks++) {
                int cbb = ks * 32;
                unsigned ah[2][4], bh[4][2], bx[4][2], tmp[4];
#pragma unroll
                for (int mi = 0; mi < 2; mi++) {
                    int rb = wm * 32 + mi * 16;
                    ldsm4(ah[mi], AhU + (rb + a_roff) * PITCHB + cbb + a_coff);
                }
#pragma unroll
                for (int p = 0; p < 2; p++) {
                    int nb = wn * 32 + p * 16;
                    ldsm4(tmp, BhU + (nb + b_roff) * PITCHB + cbb + b_coff);
                    bh[2*p][0] = tmp[0]; bh[2*p][1] = tmp[1];
                    bh[2*p+1][0] = tmp[2]; bh[2*p+1][1] = tmp[3];
                }
#pragma unroll
                for (int mi = 0; mi < 2; mi++)
#pragma unroll
                    for (int ni = 0; ni < 4; ni++) mma16816(acc[mi][ni], ah[mi], bh[ni]);
#pragma unroll
                for (int p = 0; p < 2; p++) {
                    int nb = wn * 32 + p * 16;
                    ldsm4(tmp, BlU + (nb + b_roff) * PITCHB + cbb + b_coff);
                    bx[2*p][0] = tmp[0]; bx[2*p][1] = tmp[1];
                    bx[2*p+1][0] = tmp[2]; bx[2*p+1][1] = tmp[3];
                }
#pragma unroll
                for (int mi = 0; mi < 2; mi++)
#pragma unroll
                    for (int ni = 0; ni < 4; ni++) mma16816(acc[mi][ni], ah[mi], bx[ni]);
#pragma unroll
                for (int mi = 0; mi < 2; mi++) {
                    int rb = wm * 32 + mi * 16;
                    ldsm4(ah[mi], AlU + (rb + a_roff) * PITCHB + cbb + a_coff);
                }
#pragma unroll
                for (int mi = 0; mi < 2; mi++)
#pragma unroll
                    for (int ni = 0; ni < 4; ni++) mma16816(acc[mi][ni], ah[mi], bh[ni]);
            }
            __syncthreads();
        }

        int h = (bn + wn * 32) >> 5;
        const float* ksp = g_KV + (size_t)(n * HH + h) * 1056 + 1024;
#pragma unroll
        for (int mi = 0; mi < 2; mi++) {
            int r0 = bm + wm * 32 + mi * 16 + g;
            int r1 = r0 + 8;
            float mv0 = mask_val(mask, r0), mv1 = mask_val(mask, r1);
            float cb[4][4];
            float p0 = 0.f, p1 = 0.f;
#pragma unroll
            for (int ni = 0; ni < 4; ni++) {
                int col = bn + wn * 32 + ni * 8 + tc * 2;
                int d = ni * 8 + tc * 2;
                float b0 = bias[col], b1 = bias[col + 1];
                float c0 = acc[mi][ni][0] + b0, c1 = acc[mi][ni][1] + b1;
                float c2 = acc[mi][ni][2] + b0, c3 = acc[mi][ni][3] + b1;
                c0 = (c0 > 0.f ? c0 + 1.f : expf(c0)) * mv0;
                c1 = (c1 > 0.f ? c1 + 1.f : expf(c1)) * mv0;
                c2 = (c2 > 0.f ? c2 + 1.f : expf(c2)) * mv1;
                c3 = (c3 > 0.f ? c3 + 1.f : expf(c3)) * mv1;
                float k0 = ksp[d], k1 = ksp[d + 1];
                p0 += c0 * k0 + c1 * k1;
                p1 += c2 * k0 + c3 * k1;
                cb[ni][0] = c0; cb[ni][1] = c1; cb[ni][2] = c2; cb[ni][3] = c3;
            }
            p0 += __shfl_xor_sync(0xffffffffu, p0, 1);
            p0 += __shfl_xor_sync(0xffffffffu, p0, 2);
            p1 += __shfl_xor_sync(0xffffffffu, p1, 1);
            p1 += __shfl_xor_sync(0xffffffffu, p1, 2);
            float z0 = 1.f / (p0 + EPSV), z1 = 1.f / (p1 + EPSV);
            int lr0 = wm * 32 + mi * 16 + g, lr1 = lr0 + 8;
#pragma unroll
            for (int ni = 0; ni < 4; ni++) {
                int col = bn + wn * 32 + ni * 8 + tc * 2;
                int kcb = col >> 6, cc = col & 63;
                uint2 s0 = splitpack(cb[ni][0] * z0, cb[ni][1] * z0);
                uint2 s1 = splitpack(cb[ni][2] * z1, cb[ni][3] * z1);
                uint32_t base = QsU + kcb * 36864 + cc * 2;
                asm volatile("st.shared.b32 [%0], %1;" :: "r"(base + lr0 * PITCHB), "r"(s0.x) : "memory");
                asm volatile("st.shared.b32 [%0], %1;" :: "r"(base + lr0 * PITCHB + TILEB), "r"(s0.y) : "memory");
                asm volatile("st.shared.b32 [%0], %1;" :: "r"(base + lr1 * PITCHB), "r"(s1.x) : "memory");
                asm volatile("st.shared.b32 [%0], %1;" :: "r"(base + lr1 * PITCHB + TILEB), "r"(s1.y) : "memory");
            }
        }
    }

    // ---------- Phase 2: (Qf*Z) @ UT^T, A resident in smem ----------
    const ushortT* UT = g_UTsp + (size_t)n * MATU;
    for (int bn2 = 0; bn2 < 2; bn2++) {
        float acc[2][4][4];
#pragma unroll
        for (int mi = 0; mi < 2; mi++)
#pragma unroll
            for (int ni = 0; ni < 4; ni++)
#pragma unroll
                for (int j = 0; j < 4; j++) acc[mi][ni][j] = 0.f;

#define ISSUE_UT(kc, st) do { \
        const char* _src = (const char*)(UT + (size_t)(bn2 * 4 + (kc)) * 18432); \
        uint32_t _db = (st) ? BbU : (QsU + CONV_OFF); \
        _Pragma("unroll") \
        for (int _j = 0; _j < 5; _j++) { \
            int _id = tid + _j * 512; \
            if (_id < 2304) \
                asm volatile("cp.async.cg.shared.global [%0], [%1], 16;" \
                    :: "r"(_db + _id * 16), "l"(_src + _id * 16)); \
        } \
        asm volatile("cp.async.commit_group;" ::: "memory"); \
    } while (0)

        ISSUE_UT(0, 0);
        ISSUE_UT(1, 1);

        for (int kc = 0; kc < 4; kc++) {
            int st = kc & 1;
            if (kc == 3) asm volatile("cp.async.wait_group 0;" ::: "memory");
            else         asm volatile("cp.async.wait_group 1;" ::: "memory");
            __syncthreads();
            uint32_t Ah2 = QsU + kc * 36864, Al2 = Ah2 + TILEB;
            uint32_t Bh2 = st ? BbU : (QsU + CONV_OFF), Bl2 = Bh2 + TILEB;
#pragma unroll
            for (int ks = 0; ks < 4; ks++) {
                int cbb = ks * 32;
                unsigned ah[2][4], bh[4][2], bx[4][2], tmp[4];
#pragma unroll
                for (int mi = 0; mi < 2; mi++) {
                    int rb = wm * 32 + mi * 16;
                    ldsm4(ah[mi], Ah2 + (rb + a_roff) * PITCHB + cbb + a_coff);
                }
#pragma unroll
                for (int p = 0; p < 2; p++) {
                    int nb = wn * 32 + p * 16;
                    ldsm4(tmp, Bh2 + (nb + b_roff) * PITCHB + cbb + b_coff);
                    bh[2*p][0] = tmp[0]; bh[2*p][1] = tmp[1];
                    bh[2*p+1][0] = tmp[2]; bh[2*p+1][1] = tmp[3];
                }
#pragma unroll
                for (int mi = 0; mi < 2; mi++)
#pragma unroll
                    for (int ni = 0; ni < 4; ni++) mma16816(acc[mi][ni], ah[mi], bh[ni]);
#pragma unroll
                for (int p = 0; p < 2; p++) {
                    int nb = wn * 32 + p * 16;
                    ldsm4(tmp, Bl2 + (nb + b_roff) * PITCHB + cbb + b_coff);
                    bx[2*p][0] = tmp[0]; bx[2*p][1] = tmp[1];
                    bx[2*p+1][0] = tmp[2]; bx[2*p+1][1] = tmp[3];
                }
#pragma unroll
                for (int mi = 0; mi < 2; mi++)
#pragma unroll
                    for (int ni = 0; ni < 4; ni++) mma16816(acc[mi][ni], ah[mi], bx[ni]);
#pragma unroll
                for (int mi = 0; mi < 2; mi++) {
                    int rb = wm * 32 + mi * 16;
                    ldsm4(ah[mi], Al2 + (rb + a_roff) * PITCHB + cbb + a_coff);
                }
#pragma unroll
                for (int mi = 0; mi < 2; mi++)
#pragma unroll
                    for (int ni = 0; ni < 4; ni++) mma16816(acc[mi][ni], ah[mi], bh[ni]);
            }
            __syncthreads();
            if (kc < 2) ISSUE_UT(kc + 2, st);
        }
#undef ISSUE_UT

#pragma unroll
        for (int mi = 0; mi < 2; mi++) {
            int r0 = bm + wm * 32 + mi * 16 + g;
            int r1 = r0 + 8;
#pragma unroll
            for (int ni = 0; ni < 4; ni++) {
                int col = bn2 * 128 + wn * 32 + ni * 8 + tc * 2;
                *(float2*)&Cout[(size_t)r0 * EE + col] = make_float2(acc[mi][ni][0], acc[mi][ni][1]);
                *(float2*)&Cout[(size_t)r1 * EE + col] = make_float2(acc[mi][ni][2], acc[mi][ni][3]);
            }
        }
    }
}

// ---------------- KV aggregation: double-buffered cp.async + register tiles ----------------
// dyn smem: 2 stages x (K 8192 + V 8192) = 32768; red buffer 16896 at offset 32768
#define KVSTG 16384
#define SMEM_KVP (2*KVSTG + 16896)

__global__ __launch_bounds__(256) void kv_partial() {
    int nh = blockIdx.x;
    int n = nh >> 3, h = nh & 7;
    int chunk = blockIdx.y;
    uint32_t sb = smem_u32(dyn_smem);
    float* red = (float*)(dyn_smem + 2 * KVSTG);   // [4][1056]

    int tid = threadIdx.x;
    int grp = tid >> 6;
    int gt = tid & 63;
    int dg = gt >> 3;
    int vg = gt & 7;
    float acc[4][4] = {};
    float ks[4] = {};
    int s0base = chunk * CHS;
    const float* Kp = g_Kf + (size_t)n * SS * EE + h * DD;
    const float* Vp = g_Vm + (size_t)n * SS * EE + h * DD;

    int l_row = tid >> 3, l_c = (tid & 7) * 4;     // thread's 2 row-slots
    int l_row2 = l_row + 32;

#define KVISSUE(t, st) do { \
        size_t _g0 = (size_t)(s0base + (t) * 64 + l_row) * EE + l_c; \
        size_t _g1 = (size_t)(s0base + (t) * 64 + l_row2) * EE + l_c; \
        uint32_t _d = sb + (st) * KVSTG; \
        asm volatile("cp.async.cg.shared.global [%0], [%1], 16;" \
            :: "r"(_d + (l_row * 32 + l_c) * 4), "l"(Kp + _g0)); \
        asm volatile("cp.async.cg.shared.global [%0], [%1], 16;" \
            :: "r"(_d + (l_row2 * 32 + l_c) * 4), "l"(Kp + _g1)); \
        asm volatile("cp.async.cg.shared.global [%0], [%1], 16;" \
            :: "r"(_d + 8192 + (l_row * 32 + l_c) * 4), "l"(Vp + _g0)); \
        asm volatile("cp.async.cg.shared.global [%0], [%1], 16;" \
            :: "r"(_d + 8192 + (l_row2 * 32 + l_c) * 4), "l"(Vp + _g1)); \
        asm volatile("cp.async.commit_group;" ::: "memory"); \
    } while (0)

    KVISSUE(0, 0);
    KVISSUE(1, 1);

    const int NT = CHS / 64;   // 8 tiles
    for (int t = 0; t < NT; t++) {
        int st = t & 1;
        if (t == NT - 1) asm volatile("cp.async.wait_group 0;" ::: "memory");
        else             asm volatile("cp.async.wait_group 1;" ::: "memory");
        __syncthreads();
        const float* Ks = (const float*)(dyn_smem + st * KVSTG);
        const float* Vs = Ks + 2048;
#pragma unroll
        for (int si = 0; si < 16; si++) {
            int s = grp * 16 + si;
            float4 kk = *(const float4*)&Ks[s * 32 + dg * 4];
            float4 vv = *(const float4*)&Vs[s * 32 + vg * 4];
            float ka[4] = {kk.x, kk.y, kk.z, kk.w};
            float va[4] = {vv.x, vv.y, vv.z, vv.w};
#pragma unroll
            for (int i = 0; i < 4; i++) {
                ks[i] += ka[i];
#pragma unroll
                for (int j = 0; j < 4; j++) acc[i][j] += ka[i] * va[j];
            }
        }
        __syncthreads();
        if (t < NT - 2) KVISSUE(t + 2, st);
    }
#undef KVISSUE

#pragma unroll
    for (int i = 0; i < 4; i++)
#pragma unroll
        for (int j = 0; j < 4; j++)
            red[grp * 1056 + (dg * 4 + i) * 32 + vg * 4 + j] = acc[i][j];
    if (vg == 0) {
#pragma unroll
        for (int i = 0; i < 4; i++) red[grp * 1056 + 1024 + dg * 4 + i] = ks[i];
    }
    __syncthreads();
    float* P = g_part + ((size_t)chunk * 64 + nh) * 1056;
    for (int i = tid; i < 1056; i += 256)
        P[i] = red[i] + red[1056 + i] + red[2112 + i] + red[3168 + i];
}

// ---------------- fused: reduce partials + write Ksum + emit split-bf16 UT ----------------
__global__ __launch_bounds__(256) void finalize_kv(const float* __restrict__ Wm) {
    int nh = blockIdx.x; int n = nh >> 3, h = nh & 7;
    __shared__ float KVs[32][32];
    int tid = threadIdx.x;
    for (int i = tid; i < 1056; i += 256) {
        float s = 0;
#pragma unroll
        for (int c = 0; c < NCHUNK; c++) s += g_part[((size_t)c * 64 + nh) * 1056 + i];
        if (i < 1024) KVs[i >> 5][i & 31] = s;
        else g_KV[(size_t)nh * 1056 + i] = s;
    }
    __syncthreads();
    int ep = tid;
    float w[32];
#pragma unroll
    for (int v = 0; v < 32; v++) w[v] = Wm[(size_t)ep * EE + h * DD + v];
    ushortT* dsth = g_UTsp + (size_t)n * MATU
                  + ((size_t)((ep >> 7) * 4 + (h >> 1))) * 18432
                  + (ep & 127) * 72 + (h & 1) * 32;
#pragma unroll
    for (int d2 = 0; d2 < 32; d2++) {
        float a = 0;
#pragma unroll
        for (int v = 0; v < 32; v++) a += KVs[d2][v] * w[v];
        a *= (float)SS;
        __nv_bfloat16 hb = __float2bfloat16(a);
        float hr = __bfloat162float(hb);
        __nv_bfloat16 lb = __float2bfloat16(a - hr);
        dsth[d2] = __bfloat16_as_ushort(hb);
        dsth[9216 + d2] = __bfloat16_as_ushort(lb);
    }
}

// ---------------- launch ----------------
extern "C" void kernel_launch(void* const* d_in, const int* in_sizes, int n_in,
                              void* d_out, int out_size) {
    const float* q  = (const float*)d_in[0];
    const float* k  = (const float*)d_in[1];
    const float* v  = (const float*)d_in[2];
    const void*  qm = d_in[3];
    const void*  km = d_in[4];
    const float* Wq = (const float*)d_in[5];
    const float* bq = (const float*)d_in[6];
    const float* Wk = (const float*)d_in[7];
    const float* bk = (const float*)d_in[8];
    const float* Wv = (const float*)d_in[9];
    const float* bv = (const float*)d_in[10];
    const float* Wm = (const float*)d_in[11];
    float* out = (float*)d_out;

    float *Kf, *Vm;
    ushortT *Wsp;
    cudaGetSymbolAddress((void**)&Kf, g_Kf);
    cudaGetSymbolAddress((void**)&Vm, g_Vm);
    cudaGetSymbolAddress((void**)&Wsp, g_Wsp);

    cudaFuncSetAttribute(tgemm, cudaFuncAttributeMaxDynamicSharedMemorySize, SMEM_SZ);
    cudaFuncSetAttribute(qout, cudaFuncAttributeMaxDynamicSharedMemorySize, SMEM_QO);
    cudaFuncSetAttribute(kv_partial, cudaFuncAttributeMaxDynamicSharedMemorySize, SMEM_KVP);

    detect_mask_kernel<<<1, 256>>>((const unsigned int*)km, 2048);
    split_w3<<<dim3(16, 3), 256>>>(Wq, Wk, Wv);

    // K and V projections (fused, z = 2)
    tgemm<<<dim3(2, NTOK / 128, 2), 512, SMEM_SZ>>>(
        k, v, Wsp + MATU, MATU,
        bk, bv, Kf, Vm,
        EPI_FEAT, EPI_VPROJ,
        km, 1.f / (float)SS);

    kv_partial<<<dim3(64, NCHUNK), 256, SMEM_KVP>>>();
    finalize_kv<<<64, 256>>>(Wm);

    // fused Q-projection (with Z fold) + final merge GEMM
    qout<<<NTOK / 128, 512, SMEM_QO>>>(q, bq, out, qm);
}

// round 16
// speedup vs baseline: 1.4960x; 1.0016x over previous
#include <cuda_runtime.h>
#include <cuda_bf16.h>
#include <cstdint>

#define Nb 8
#define LL 4096
#define SS 4096
#define EE 256
#define HH 8
#define DD 32
#define NTOK (Nb*LL)
#define EPSV 1e-6f
#define NCHUNK 8
#define CHS (SS/NCHUNK)

typedef unsigned short ushortT;

// ---------------- scratch ----------------
__device__ float g_Kf[Nb*SS*EE];
__device__ float g_Vm[Nb*SS*EE];
__device__ float g_part[NCHUNK*Nb*HH*1056];
__device__ float g_KV[Nb*HH*1056];     // Ksum at [1024..1055]
__device__ int   g_mask_kind;
#define MATU 147456                    // ushorts per 256x256 split matrix
__device__ ushortT g_Wsp[3*MATU];      // Wq, Wk, Wv  (tiled hi/lo bf16)
__device__ ushortT g_UTsp[Nb*MATU];    // per-batch UT (tiled hi/lo bf16)

// ---------------- helpers ----------------
__device__ __forceinline__ uint32_t smem_u32(const void* p) {
    uint32_t a;
    asm("{ .reg .u64 t; cvta.to.shared.u64 t, %1; cvt.u32.u64 %0, t; }" : "=r"(a) : "l"(p));
    return a;
}
__device__ __forceinline__ void ldsm4(unsigned* r, uint32_t addr) {
    asm volatile("ldmatrix.sync.aligned.m8n8.x4.shared.b16 {%0,%1,%2,%3}, [%4];"
        : "=r"(r[0]), "=r"(r[1]), "=r"(r[2]), "=r"(r[3]) : "r"(addr));
}
__device__ __forceinline__ void mma16816(float* c, const unsigned* a, const unsigned* b) {
    asm volatile("mma.sync.aligned.m16n8k16.row.col.f32.bf16.bf16.f32 "
        "{%0,%1,%2,%3}, {%4,%5,%6,%7}, {%8,%9}, {%0,%1,%2,%3};"
        : "+f"(c[0]), "+f"(c[1]), "+f"(c[2]), "+f"(c[3])
        : "r"(a[0]), "r"(a[1]), "r"(a[2]), "r"(a[3]), "r"(b[0]), "r"(b[1]));
}
__device__ __forceinline__ uint2 splitpack(float x0, float x1) {
    __nv_bfloat162 h = __float22bfloat162_rn(make_float2(x0, x1));
    float2 hf = __bfloat1622float2(h);
    __nv_bfloat162 l = __float22bfloat162_rn(make_float2(x0 - hf.x, x1 - hf.y));
    uint2 o;
    o.x = *(unsigned*)&h;
    o.y = *(unsigned*)&l;
    return o;
}

__device__ __forceinline__ float mask_val(const void* p, int i) {
    int k = g_mask_kind;
    if (k == 0) return ((const unsigned char*)p)[i] ? 1.f : 0.f;
    if (k == 1) return ((const int*)p)[i] ? 1.f : 0.f;
    if (k == 2) return ((const float*)p)[i];
    return __bfloat162float(((const __nv_bfloat16*)p)[i]);
}

// ---------------- pre-split the 3 weight matrices + mask detection (fused) ----------------
__global__ __launch_bounds__(256) void split_w3(const float* __restrict__ W0,
                                                const float* __restrict__ W1,
                                                const float* __restrict__ W2,
                                                const unsigned int* __restrict__ m) {
    if (blockIdx.x == 16) {
        if (blockIdx.y != 0) return;
        __shared__ int flags[3];
        if (threadIdx.x < 3) flags[threadIdx.x] = 0;
        __syncthreads();
        for (int i = threadIdx.x; i < 2048; i += blockDim.x) {
            unsigned w = m[i];
            if (w == 0x3F803F80u || w == 0x00003F80u) atomicOr(&flags[0], 1);
            else if (w == 0x3F800000u) atomicOr(&flags[1], 1);
            else if (w > 1u) {
                unsigned b0 = w & 255u, b1 = (w >> 8) & 255u, b2 = (w >> 16) & 255u, b3 = w >> 24;
                if (b0 <= 1u && b1 <= 1u && b2 <= 1u && b3 <= 1u) atomicOr(&flags[2], 1);
            }
        }
        __syncthreads();
        if (threadIdx.x == 0) {
            int kind;
            if (flags[0]) kind = 3;
            else if (flags[1]) kind = 2;
            else if (flags[2]) kind = 0;
            else kind = 1;
            g_mask_kind = kind;
        }
        return;
    }
    int y = blockIdx.y;
    const float* src = y == 0 ? W0 : (y == 1 ? W1 : W2);
    ushortT* dst = g_Wsp + (size_t)y * MATU;
    int blk = blockIdx.x >> 1;
    int half = blockIdx.x & 1;
    int nh2 = blk >> 2, kc = blk & 3;
    int tid = threadIdx.x;
    size_t ubase = (size_t)blk * 18432;
#pragma unroll
    for (int i = 0; i < 4; i++) {
        int idx = tid + i * 256;
        int r = half * 64 + (idx >> 4), c4 = (idx & 15) * 4;
        float4 v = *(const float4*)&src[(size_t)(nh2 * 128 + r) * EE + kc * 64 + c4];
        uint2 s0 = splitpack(v.x, v.y);
        uint2 s1 = splitpack(v.z, v.w);
        ushortT* hp = dst + ubase + r * 72 + c4;
        *(unsigned*)hp = s0.x; *(unsigned*)(hp + 2) = s1.x;
        ushortT* lp = hp + 9216;
        *(unsigned*)lp = s0.y; *(unsigned*)(lp + 2) = s1.y;
    }
}

// ================= pipelined mma.sync split-bf16 GEMM (K/V projections) =================
#define EPI_FEAT  1
#define EPI_VPROJ 2
#define PITCHB 144
#define TILEB (128*PITCHB)    // 18432 B
#define BSTAGE (2*TILEB)
#define SMEM_SZ (2*TILEB + 2*BSTAGE)   // 110592 B

extern __shared__ char dyn_smem[];

__global__ void __launch_bounds__(512, 2) tgemm(
    const float* __restrict__ A0, const float* __restrict__ A1,
    const ushortT* __restrict__ Bsp, int bStrideZ,
    const float* __restrict__ bias0, const float* __restrict__ bias1,
    float* __restrict__ C0, float* __restrict__ C1,
    int epi0, int epi1,
    const void* __restrict__ mask, float scale)
{
    int z = blockIdx.z;
    const float* A    = z == 0 ? A0 : A1;
    const float* bias = z == 0 ? bias0 : bias1;
    float* C          = z == 0 ? C0 : C1;
    int epi           = z == 0 ? epi0 : epi1;

    uint32_t AhU = smem_u32(dyn_smem);
    uint32_t AlU = AhU + TILEB;
    uint32_t BsU = AhU + 2 * TILEB;

    int tid = threadIdx.x, wid = tid >> 5, lane = tid & 31;
    int wm = wid >> 2, wn = wid & 3;
    int bm = blockIdx.y * 128, bn = blockIdx.x * 128;
    const ushortT* B = Bsp + (size_t)z * bStrideZ;

    int lmat = lane >> 3, lrow = lane & 7;
    int a_roff = ((lmat & 1) ? 8 : 0) + lrow;
    int a_coff = (lmat & 2) ? 16 : 0;
    int b_roff = ((lmat & 2) ? 8 : 0) + lrow;
    int b_coff = (lmat & 1) ? 16 : 0;

    float acc[2][4][4];
#pragma unroll
    for (int mi = 0; mi < 2; mi++)
#pragma unroll
        for (int ni = 0; ni < 4; ni++)
#pragma unroll
            for (int j = 0; j < 4; j++) acc[mi][ni][j] = 0.f;

    float4 pf[4];

#define ISSUE_B(kc, stage) do { \
        const char* _src = (const char*)(B + (size_t)(blockIdx.x * 4 + (kc)) * 18432); \
        uint32_t _db = BsU + (stage) * BSTAGE; \
        _Pragma("unroll") \
        for (int _j = 0; _j < 5; _j++) { \
            int _id = tid + _j * 512; \
            if (_id < 2304) \
                asm volatile("cp.async.cg.shared.global [%0], [%1], 16;" \
                    :: "r"(_db + _id * 16), "l"(_src + _id * 16)); \
        } \
        asm volatile("cp.async.commit_group;" ::: "memory"); \
    } while (0)

#define LOAD_A(kc) do { \
        _Pragma("unroll") \
        for (int _i = 0; _i < 4; _i++) { \
            int _idx = tid + _i * 512; \
            int _r = _idx >> 4, _c4 = (_idx & 15) << 2; \
            pf[_i] = *(const float4*)&A[(size_t)(bm + _r) * EE + (kc) * 64 + _c4]; \
        } \
    } while (0)

#define STORE_A() do { \
        _Pragma("unroll") \
        for (int _i = 0; _i < 4; _i++) { \
            int _idx = tid + _i * 512; \
            int _r = _idx >> 4, _c4 = (_idx & 15) << 2; \
            uint32_t _off = _r * PITCHB + _c4 * 2; \
            uint2 _s0 = splitpack(pf[_i].x, pf[_i].y); \
            uint2 _s1 = splitpack(pf[_i].z, pf[_i].w); \
            asm volatile("st.shared.v2.b32 [%0], {%1,%2};" :: "r"(AhU + _off), "r"(_s0.x), "r"(_s1.x) : "memory"); \
            asm volatile("st.shared.v2.b32 [%0], {%1,%2};" :: "r"(AlU + _off), "r"(_s0.y), "r"(_s1.y) : "memory"); \
        } \
    } while (0)

    ISSUE_B(0, 0);
    LOAD_A(0);
    STORE_A();
    asm volatile("cp.async.wait_group 0;" ::: "memory");
    __syncthreads();

    for (int kc = 0; kc < 4; kc++) {
        int s = kc & 1;
        if (kc < 3) {
            ISSUE_B(kc + 1, s ^ 1);
            LOAD_A(kc + 1);
        }
        uint32_t BhU = BsU + s * BSTAGE;
        uint32_t BlU = BhU + TILEB;
#pragma unroll
        for (int ks = 0; ks < 4; ks++) {
            int cbb = ks * 32;
            unsigned ah[2][4], bh[4][2], bx[4][2], tmp[4];
#pragma unroll
            for (int mi = 0; mi < 2; mi++) {
                int rb = wm * 32 + mi * 16;
                ldsm4(ah[mi], AhU + (rb + a_roff) * PITCHB + cbb + a_coff);
            }
#pragma unroll
            for (int p = 0; p < 2; p++) {
                int nb = wn * 32 + p * 16;
                ldsm4(tmp, BhU + (nb + b_roff) * PITCHB + cbb + b_coff);
                bh[2*p][0] = tmp[0]; bh[2*p][1] = tmp[1];
                bh[2*p+1][0] = tmp[2]; bh[2*p+1][1] = tmp[3];
            }
#pragma unroll
            for (int mi = 0; mi < 2; mi++)
#pragma unroll
                for (int ni = 0; ni < 4; ni++) mma16816(acc[mi][ni], ah[mi], bh[ni]);
#pragma unroll
            for (int p = 0; p < 2; p++) {
                int nb = wn * 32 + p * 16;
                ldsm4(tmp, BlU + (nb + b_roff) * PITCHB + cbb + b_coff);
                bx[2*p][0] = tmp[0]; bx[2*p][1] = tmp[1];
                bx[2*p+1][0] = tmp[2]; bx[2*p+1][1] = tmp[3];
            }
#pragma unroll
            for (int mi = 0; mi < 2; mi++)
#pragma unroll
                for (int ni = 0; ni < 4; ni++) mma16816(acc[mi][ni], ah[mi], bx[ni]);
#pragma unroll
            for (int mi = 0; mi < 2; mi++) {
                int rb = wm * 32 + mi * 16;
                ldsm4(ah[mi], AlU + (rb + a_roff) * PITCHB + cbb + a_coff);
            }
#pragma unroll
            for (int mi = 0; mi < 2; mi++)
#pragma unroll
                for (int ni = 0; ni < 4; ni++) mma16816(acc[mi][ni], ah[mi], bh[ni]);
        }
        __syncthreads();
        if (kc < 3) {
            STORE_A();
            asm volatile("cp.async.wait_group 0;" ::: "memory");
            __syncthreads();
        }
    }

    // ---- epilogue: EPI_FEAT / EPI_VPROJ -> fp32 row-major ----
    int g = lane >> 2, tc = lane & 3;
#pragma unroll
    for (int mi = 0; mi < 2; mi++) {
        int r0 = bm + wm * 32 + mi * 16 + g;
        int r1 = r0 + 8;
        float mv0 = mask_val(mask, r0), mv1 = mask_val(mask, r1);
#pragma unroll
        for (int ni = 0; ni < 4; ni++) {
            int col = bn + wn * 32 + ni * 8 + tc * 2;
            float c0 = acc[mi][ni][0], c1 = acc[mi][ni][1];
            float c2 = acc[mi][ni][2], c3 = acc[mi][ni][3];
            float b0 = bias[col], b1 = bias[col + 1];
            if (epi == EPI_FEAT) {
                c0 += b0; c1 += b1; c2 += b0; c3 += b1;
                c0 = (c0 > 0.f ? c0 + 1.f : expf(c0)) * mv0;
                c1 = (c1 > 0.f ? c1 + 1.f : expf(c1)) * mv0;
                c2 = (c2 > 0.f ? c2 + 1.f : expf(c2)) * mv1;
                c3 = (c3 > 0.f ? c3 + 1.f : expf(c3)) * mv1;
            } else {
                c0 = (c0 + b0) * mv0 * scale; c1 = (c1 + b1) * mv0 * scale;
                c2 = (c2 + b0) * mv1 * scale; c3 = (c3 + b1) * mv1 * scale;
            }
            *(float2*)&C[(size_t)r0 * EE + col] = make_float2(c0, c1);
            *(float2*)&C[(size_t)r1 * EE + col] = make_float2(c2, c3);
        }
    }
#undef ISSUE_B
#undef LOAD_A
#undef STORE_A
}

// ================= fused Q-projection + Z-fold + final GEMM =================
#define QSP_BYTES 147456
#define CONV_OFF 147456
#define BBUF_OFF 184320
#define SMEM_QO 221184

__global__ void __launch_bounds__(512) qout(
    const float* __restrict__ A, const float* __restrict__ bias,
    float* __restrict__ Cout, const void* __restrict__ mask)
{
    uint32_t QsU = smem_u32(dyn_smem);
    uint32_t AhU = QsU + CONV_OFF;
    uint32_t AlU = AhU + TILEB;
    uint32_t BbU = QsU + BBUF_OFF;

    int tid = threadIdx.x, wid = tid >> 5, lane = tid & 31;
    int wm = wid >> 2, wn = wid & 3;
    int bm = blockIdx.x * 128;
    int n = bm >> 12;

    int lmat = lane >> 3, lrow = lane & 7;
    int a_roff = ((lmat & 1) ? 8 : 0) + lrow;
    int a_coff = (lmat & 2) ? 16 : 0;
    int b_roff = ((lmat & 2) ? 8 : 0) + lrow;
    int b_coff = (lmat & 1) ? 16 : 0;
    int g = lane >> 2, tc = lane & 3;

    float4 pf[4];
    uint4 breg[5];

#define LOAD_AQ(kc) do { \
        _Pragma("unroll") \
        for (int _i = 0; _i < 4; _i++) { \
            int _idx = tid + _i * 512; \
            int _r = _idx >> 4, _c4 = (_idx & 15) << 2; \
            pf[_i] = *(const float4*)&A[(size_t)(bm + _r) * EE + (kc) * 64 + _c4]; \
        } \
    } while (0)

#define STORE_AQ() do { \
        _Pragma("unroll") \
        for (int _i = 0; _i < 4; _i++) { \
            int _idx = tid + _i * 512; \
            int _r = _idx >> 4, _c4 = (_idx & 15) << 2; \
            uint32_t _off = _r * PITCHB + _c4 * 2; \
            uint2 _s0 = splitpack(pf[_i].x, pf[_i].y); \
            uint2 _s1 = splitpack(pf[_i].z, pf[_i].w); \
            asm volatile("st.shared.v2.b32 [%0], {%1,%2};" :: "r"(AhU + _off), "r"(_s0.x), "r"(_s1.x) : "memory"); \
            asm volatile("st.shared.v2.b32 [%0], {%1,%2};" :: "r"(AlU + _off), "r"(_s0.y), "r"(_s1.y) : "memory"); \
        } \
    } while (0)

#define LOADB_REG(bidx) do { \
        const uint4* _bs = (const uint4*)(g_Wsp + (size_t)(bidx) * 18432); \
        _Pragma("unroll") \
        for (int _j = 0; _j < 5; _j++) { \
            int _id = tid + _j * 512; \
            if (_id < 2304) breg[_j] = _bs[_id]; \
        } \
    } while (0)

#define STOREB_REG() do { \
        _Pragma("unroll") \
        for (int _j = 0; _j < 5; _j++) { \
            int _id = tid + _j * 512; \
            if (_id < 2304) \
                asm volatile("st.shared.v4.b32 [%0], {%1,%2,%3,%4};" \
                    :: "r"(BbU + _id * 16), "r"(breg[_j].x), "r"(breg[_j].y), \
                       "r"(breg[_j].z), "r"(breg[_j].w) : "memory"); \
        } \
    } while (0)

    // ---------- Phase 1: Qf*Z -> Qsp (smem), two 128-col passes ----------
    for (int bn2 = 0; bn2 < 2; bn2++) {
        int bn = bn2 * 128;
        float acc[2][4][4];
#pragma unroll
        for (int mi = 0; mi < 2; mi++)
#pragma unroll
            for (int ni = 0; ni < 4; ni++)
#pragma unroll
                for (int j = 0; j < 4; j++) acc[mi][ni][j] = 0.f;

        // prologue: B(kc=0) via cp.async, A(kc=0) convert
        {
            const char* src = (const char*)(g_Wsp + (size_t)(bn2 * 4) * 18432);
#pragma unroll
            for (int j = 0; j < 5; j++) {
                int id = tid + j * 512;
                if (id < 2304)
                    asm volatile("cp.async.cg.shared.global [%0], [%1], 16;"
                        :: "r"(BbU + id * 16), "l"(src + id * 16));
            }
            asm volatile("cp.async.commit_group;" ::: "memory");
        }
        LOAD_AQ(0);
        STORE_AQ();
        asm volatile("cp.async.wait_group 0;" ::: "memory");
        __syncthreads();

        for (int kc = 0; kc < 4; kc++) {
            if (kc < 3) {                      // prefetch next A and B into regs
                LOADB_REG(bn2 * 4 + kc + 1);
                LOAD_AQ(kc + 1);
            }
            uint32_t BhU = BbU, BlU = BbU + TILEB;
#pragma unroll
            for (int ks = 0; ks < 4; ks++) {
                int cbb = ks * 32;
                unsigned ah[2][4], bh[4][2], bx[4][2], tmp[4];
#pragma unroll
                for (int mi = 0; mi < 2; mi++) {
                    int rb = wm * 32 + mi * 16;
                    ldsm4(ah[mi], AhU + (rb + a_roff) * PITCHB + cbb + a_coff);
                }
#pragma unroll
                for (int p = 0; p < 2; p++) {
                    int nb = wn * 32 + p * 16;
                    ldsm4(tmp, BhU + (nb + b_roff) * PITCHB + cbb + b_coff);
                    bh[2*p][0] = tmp[0]; bh[2*p][1] = tmp[1];
                    bh[2*p+1][0] = tmp[2]; bh[2*p+1][1] = tmp[3];
                }
#pragma unroll
                for (int mi = 0; mi < 2; mi++)
#pragma unroll
                    for (int ni = 0; ni < 4; ni++) mma16816(acc[mi][ni], ah[mi], bh[ni]);
#pragma unroll
                for (int p = 0; p < 2; p++) {
                    int nb = wn * 32 + p * 16;
                    ldsm4(tmp, BlU + (nb + b_roff) * PITCHB + cbb + b_coff);
                    bx[2*p][0] = tmp[0]; bx[2*p][1] = tmp[1];
                    bx[2*p+1][0] = tmp[2]; bx[2*p+1][1] = tmp[3];
                }
#pragma unroll
                for (int mi = 0; mi < 2; mi++)
#pragma unroll
                    for (int ni = 0; ni < 4; ni++) mma16816(acc[mi][ni], ah[mi], bx[ni]);
#pragma unroll
                for (int mi = 0; mi < 2; mi++) {
                    int rb = wm * 32 + mi * 16;
                    ldsm4(ah[mi], AlU + (rb + a_roff) * PITCHB + cbb + a_coff);
                }
#pragma unroll
                for (int mi = 0; mi < 2; mi++)
#pragma unroll
                    for (int ni = 0; ni < 4; ni++) mma16816(acc[mi][ni], ah[mi], bh[ni]);
            }
            __syncthreads();
            if (kc < 3) {
                STORE_AQ();
                STOREB_REG();
                __syncthreads();
            }
        }

        int h = (bn + wn * 32) >> 5;
        const float* ksp = g_KV + (size_t)(n * HH + h) * 1056 + 1024;
#pragma unroll
        for (int mi = 0; mi < 2; mi++) {
            int r0 = bm + wm * 32 + mi * 16 + g;
            int r1 = r0 + 8;
            float mv0 = mask_val(mask, r0), mv1 = mask_val(mask, r1);
            float cb[4][4];
            float p0 = 0.f, p1 = 0.f;
#pragma unroll
            for (int ni = 0; ni < 4; ni++) {
                int col = bn + wn * 32 + ni * 8 + tc * 2;
                int d = ni * 8 + tc * 2;
                float b0 = bias[col], b1 = bias[col + 1];
                float c0 = acc[mi][ni][0] + b0, c1 = acc[mi][ni][1] + b1;
                float c2 = acc[mi][ni][2] + b0, c3 = acc[mi][ni][3] + b1;
                c0 = (c0 > 0.f ? c0 + 1.f : expf(c0)) * mv0;
                c1 = (c1 > 0.f ? c1 + 1.f : expf(c1)) * mv0;
                c2 = (c2 > 0.f ? c2 + 1.f : expf(c2)) * mv1;
                c3 = (c3 > 0.f ? c3 + 1.f : expf(c3)) * mv1;
                float k0 = ksp[d], k1 = ksp[d + 1];
                p0 += c0 * k0 + c1 * k1;
                p1 += c2 * k0 + c3 * k1;
                cb[ni][0] = c0; cb[ni][1] = c1; cb[ni][2] = c2; cb[ni][3] = c3;
            }
            p0 += __shfl_xor_sync(0xffffffffu, p0, 1);
            p0 += __shfl_xor_sync(0xffffffffu, p0, 2);
            p1 += __shfl_xor_sync(0xffffffffu, p1, 1);
            p1 += __shfl_xor_sync(0xffffffffu, p1, 2);
            float z0 = 1.f / (p0 + EPSV), z1 = 1.f / (p1 + EPSV);
            int lr0 = wm * 32 + mi * 16 + g, lr1 = lr0 + 8;
#pragma unroll
            for (int ni = 0; ni < 4; ni++) {
                int col = bn + wn * 32 + ni * 8 + tc * 2;
                int kcb = col >> 6, cc = col & 63;
                uint2 s0 = splitpack(cb[ni][0] * z0, cb[ni][1] * z0);
                uint2 s1 = splitpack(cb[ni][2] * z1, cb[ni][3] * z1);
                uint32_t base = QsU + kcb * 36864 + cc * 2;
                asm volatile("st.shared.b32 [%0], %1;" :: "r"(base + lr0 * PITCHB), "r"(s0.x) : "memory");
                asm volatile("st.shared.b32 [%0], %1;" :: "r"(base + lr0 * PITCHB + TILEB), "r"(s0.y) : "memory");
                asm volatile("st.shared.b32 [%0], %1;" :: "r"(base + lr1 * PITCHB), "r"(s1.x) : "memory");
                asm volatile("st.shared.b32 [%0], %1;" :: "r"(base + lr1 * PITCHB + TILEB), "r"(s1.y) : "memory");
            }
        }
    }

    // ---------- Phase 2: (Qf*Z) @ UT^T, A resident in smem ----------
    const ushortT* UT = g_UTsp + (size_t)n * MATU;
    for (int bn2 = 0; bn2 < 2; bn2++) {
        float acc[2][4][4];
#pragma unroll
        for (int mi = 0; mi < 2; mi++)
#pragma unroll
            for (int ni = 0; ni < 4; ni++)
#pragma unroll
                for (int j = 0; j < 4; j++) acc[mi][ni][j] = 0.f;

#define ISSUE_UT(kc, st) do { \
        const char* _src = (const char*)(UT + (size_t)(bn2 * 4 + (kc)) * 18432); \
        uint32_t _db = (st) ? BbU : (QsU + CONV_OFF); \
        _Pragma("unroll") \
        for (int _j = 0; _j < 5; _j++) { \
            int _id = tid + _j * 512; \
            if (_id < 2304) \
                asm volatile("cp.async.cg.shared.global [%0], [%1], 16;" \
                    :: "r"(_db + _id * 16), "l"(_src + _id * 16)); \
        } \
        asm volatile("cp.async.commit_group;" ::: "memory"); \
    } while (0)

        ISSUE_UT(0, 0);
        ISSUE_UT(1, 1);

        for (int kc = 0; kc < 4; kc++) {
            int st = kc & 1;
            if (kc == 3) asm volatile("cp.async.wait_group 0;" ::: "memory");
            else         asm volatile("cp.async.wait_group 1;" ::: "memory");
            __syncthreads();
            uint32_t Ah2 = QsU + kc * 36864, Al2 = Ah2 + TILEB;
            uint32_t Bh2 = st ? BbU : (QsU + CONV_OFF), Bl2 = Bh2 + TILEB;
#pragma unroll
            for (int ks = 0; ks < 4; ks++) {
                int cbb = ks * 32;
                unsigned ah[2][4], bh[4][2], bx[4][2], tmp[4];
#pragma unroll
                for (int mi = 0; mi < 2; mi++) {
                    int rb = wm * 32 + mi * 16;
                    ldsm4(ah[mi], Ah2 + (rb + a_roff) * PITCHB + cbb + a_coff);
                }
#pragma unroll
                for (int p = 0; p < 2; p++) {
                    int nb = wn * 32 + p * 16;
                    ldsm4(tmp, Bh2 + (nb + b_roff) * PITCHB + cbb + b_coff);
                    bh[2*p][0] = tmp[0]; bh[2*p][1] = tmp[1];
                    bh[2*p+1][0] = tmp[2]; bh[2*p+1][1] = tmp[3];
                }
#pragma unroll
                for (int mi = 0; mi < 2; mi++)
#pragma unroll
                    for (int ni = 0; ni < 4; ni++) mma16816(acc[mi][ni], ah[mi], bh[ni]);
#pragma unroll
                for (int p = 0; p < 2; p++) {
                    int nb = wn * 32 + p * 16;
                    ldsm4(tmp, Bl2 + (nb + b_roff) * PITCHB + cbb + b_coff);
                    bx[2*p][0] = tmp[0]; bx[2*p][1] = tmp[1];
                    bx[2*p+1][0] = tmp[2]; bx[2*p+1][1] = tmp[3];
                }
#pragma unroll
                for (int mi = 0; mi < 2; mi++)
#pragma unroll
                    for (int ni = 0; ni < 4; ni++) mma16816(acc[mi][ni], ah[mi], bx[ni]);
#pragma unroll
                for (int mi = 0; mi < 2; mi++) {
                    int rb = wm * 32 + mi * 16;
                    ldsm4(ah[mi], Al2 + (rb + a_roff) * PITCHB + cbb + a_coff);
                }
#pragma unroll
                for (int mi = 0; mi < 2; mi++)
#pragma unroll
                    for (int ni = 0; ni < 4; ni++) mma16816(acc[mi][ni], ah[mi], bh[ni]);
            }
            __syncthreads();
            if (kc < 2) ISSUE_UT(kc + 2, st);
        }
#undef ISSUE_UT

#pragma unroll
        for (int mi = 0; mi < 2; mi++) {
            int r0 = bm + wm * 32 + mi * 16 + g;
            int r1 = r0 + 8;
#pragma unroll
            for (int ni = 0; ni < 4; ni++) {
                int col = bn2 * 128 + wn * 32 + ni * 8 + tc * 2;
                *(float2*)&Cout[(size_t)r0 * EE + col] = make_float2(acc[mi][ni][0], acc[mi][ni][1]);
                *(float2*)&Cout[(size_t)r1 * EE + col] = make_float2(acc[mi][ni][2], acc[mi][ni][3]);
            }
        }
    }
#undef LOAD_AQ
#undef STORE_AQ
#undef LOADB_REG
#undef STOREB_REG
}

// ---------------- KV aggregation: double-buffered cp.async + register tiles ----------------
#define KVSTG 16384
#define SMEM_KVP (2*KVSTG + 16896)

__global__ __launch_bounds__(256) void kv_partial() {
    int nh = blockIdx.x;
    int n = nh >> 3, h = nh & 7;
    int chunk = blockIdx.y;
    uint32_t sb = smem_u32(dyn_smem);
    float* red = (float*)(dyn_smem + 2 * KVSTG);   // [4][1056]

    int tid = threadIdx.x;
    int grp = tid >> 6;
    int gt = tid & 63;
    int dg = gt >> 3;
    int vg = gt & 7;
    float acc[4][4] = {};
    float ks[4] = {};
    int s0base = chunk * CHS;
    const float* Kp = g_Kf + (size_t)n * SS * EE + h * DD;
    const float* Vp = g_Vm + (size_t)n * SS * EE + h * DD;

    int l_row = tid >> 3, l_c = (tid & 7) * 4;
    int l_row2 = l_row + 32;

#define KVISSUE(t, st) do { \
        size_t _g0 = (size_t)(s0base + (t) * 64 + l_row) * EE + l_c; \
        size_t _g1 = (size_t)(s0base + (t) * 64 + l_row2) * EE + l_c; \
        uint32_t _d = sb + (st) * KVSTG; \
        asm volatile("cp.async.cg.shared.global [%0], [%1], 16;" \
            :: "r"(_d + (l_row * 32 + l_c) * 4), "l"(Kp + _g0)); \
        asm volatile("cp.async.cg.shared.global [%0], [%1], 16;" \
            :: "r"(_d + (l_row2 * 32 + l_c) * 4), "l"(Kp + _g1)); \
        asm volatile("cp.async.cg.shared.global [%0], [%1], 16;" \
            :: "r"(_d + 8192 + (l_row * 32 + l_c) * 4), "l"(Vp + _g0)); \
        asm volatile("cp.async.cg.shared.global [%0], [%1], 16;" \
            :: "r"(_d + 8192 + (l_row2 * 32 + l_c) * 4), "l"(Vp + _g1)); \
        asm volatile("cp.async.commit_group;" ::: "memory"); \
    } while (0)

    KVISSUE(0, 0);
    KVISSUE(1, 1);

    const int NT = CHS / 64;
    for (int t = 0; t < NT; t++) {
        int st = t & 1;
        if (t == NT - 1) asm volatile("cp.async.wait_group 0;" ::: "memory");
        else             asm volatile("cp.async.wait_group 1;" ::: "memory");
        __syncthreads();
        const float* Ks = (const float*)(dyn_smem + st * KVSTG);
        const float* Vs = Ks + 2048;
#pragma unroll
        for (int si = 0; si < 16; si++) {
            int s = grp * 16 + si;
            float4 kk = *(const float4*)&Ks[s * 32 + dg * 4];
            float4 vv = *(const float4*)&Vs[s * 32 + vg * 4];
            float ka[4] = {kk.x, kk.y, kk.z, kk.w};
            float va[4] = {vv.x, vv.y, vv.z, vv.w};
#pragma unroll
            for (int i = 0; i < 4; i++) {
                ks[i] += ka[i];
#pragma unroll
                for (int j = 0; j < 4; j++) acc[i][j] += ka[i] * va[j];
            }
        }
        __syncthreads();
        if (t < NT - 2) KVISSUE(t + 2, st);
    }
#undef KVISSUE

#pragma unroll
    for (int i = 0; i < 4; i++)
#pragma unroll
        for (int j = 0; j < 4; j++)
            red[grp * 1056 + (dg * 4 + i) * 32 + vg * 4 + j] = acc[i][j];
    if (vg == 0) {
#pragma unroll
        for (int i = 0; i < 4; i++) red[grp * 1056 + 1024 + dg * 4 + i] = ks[i];
    }
    __syncthreads();
    float* P = g_part + ((size_t)chunk * 64 + nh) * 1056;
    for (int i = tid; i < 1056; i += 256)
        P[i] = red[i] + red[1056 + i] + red[2112 + i] + red[3168 + i];
}

// ---------------- fused: reduce partials + write Ksum + emit split-bf16 UT ----------------
__global__ __launch_bounds__(256) void finalize_kv(const float* __restrict__ Wm) {
    int nh = blockIdx.x; int n = nh >> 3, h = nh & 7;
    __shared__ float KVs[32][32];
    int tid = threadIdx.x;
    for (int i = tid; i < 1056; i += 256) {
        float s = 0;
#pragma unroll
        for (int c = 0; c < NCHUNK; c++) s += g_part[((size_t)c * 64 + nh) * 1056 + i];
        if (i < 1024) KVs[i >> 5][i & 31] = s;
        else g_KV[(size_t)nh * 1056 + i] = s;
    }
    __syncthreads();
    int ep = tid;
    float w[32];
#pragma unroll
    for (int v = 0; v < 32; v++) w[v] = Wm[(size_t)ep * EE + h * DD + v];
    ushortT* dsth = g_UTsp + (size_t)n * MATU
                  + ((size_t)((ep >> 7) * 4 + (h >> 1))) * 18432
                  + (ep & 127) * 72 + (h & 1) * 32;
#pragma unroll
    for (int d2 = 0; d2 < 32; d2++) {
        float a = 0;
#pragma unroll
        for (int v = 0; v < 32; v++) a += KVs[d2][v] * w[v];
        a *= (float)SS;
        __nv_bfloat16 hb = __float2bfloat16(a);
        float hr = __bfloat162float(hb);
        __nv_bfloat16 lb = __float2bfloat16(a - hr);
        dsth[d2] = __bfloat16_as_ushort(hb);
        dsth[9216 + d2] = __bfloat16_as_ushort(lb);
    }
}

// ---------------- launch ----------------
extern "C" void kernel_launch(void* const* d_in, const int* in_sizes, int n_in,
                              void* d_out, int out_size) {
    const float* q  = (const float*)d_in[0];
    const float* k  = (const float*)d_in[1];
    const float* v  = (const float*)d_in[2];
    const void*  qm = d_in[3];
    const void*  km = d_in[4];
    const float* Wq = (const float*)d_in[5];
    const float* bq = (const float*)d_in[6];
    const float* Wk = (const float*)d_in[7];
    const float* bk = (const float*)d_in[8];
    const float* Wv = (const float*)d_in[9];
    const float* bv = (const float*)d_in[10];
    const float* Wm = (const float*)d_in[11];
    float* out = (float*)d_out;

    float *Kf, *Vm;
    ushortT *Wsp;
    cudaGetSymbolAddress((void**)&Kf, g_Kf);
    cudaGetSymbolAddress((void**)&Vm, g_Vm);
    cudaGetSymbolAddress((void**)&Wsp, g_Wsp);

    cudaFuncSetAttribute(tgemm, cudaFuncAttributeMaxDynamicSharedMemorySize, SMEM_SZ);
    cudaFuncSetAttribute(qout, cudaFuncAttributeMaxDynamicSharedMemorySize, SMEM_QO);
    cudaFuncSetAttribute(kv_partial, cudaFuncAttributeMaxDynamicSharedMemorySize, SMEM_KVP);

    split_w3<<<dim3(17, 3), 256>>>(Wq, Wk, Wv, (const unsigned int*)km);

    // K and V projections (fused, z = 2)
    tgemm<<<dim3(2, NTOK / 128, 2), 512, SMEM_SZ>>>(
        k, v, Wsp + MATU, MATU,
        bk, bv, Kf, Vm,
        EPI_FEAT, EPI_VPROJ,
        km, 1.f / (float)SS);

    kv_partial<<<dim3(64, NCHUNK), 256, SMEM_KVP>>>();
    finalize_kv<<<64, 256>>>(Wm);

    // fused Q-projection (with Z fold) + final merge GEMM
    qout<<<NTOK / 128, 512, SMEM_QO>>>(q, bq, out, qm);
}